// round 1
// baseline (speedup 1.0000x reference)
#include <cuda_runtime.h>

// Problem shape (fixed by the dataset)
#define NN    100000
#define EE    1600000
#define IN_F  256
#define HID_F 64
#define OUT_F 32

// ----------------------------------------------------------------------------
// Scratch (no dynamic allocation allowed -> __device__ globals)
// ----------------------------------------------------------------------------
__device__ float g_dinv[NN];            // degree, then rsqrt(degree) in place
__device__ float g_norm[EE];            // per-edge symmetric norm
__device__ float g_t[NN * HID_F];       // x@W1, later h@[Wmu|Wlv]
__device__ float g_agg[NN * HID_F];     // layer-1 accumulator, then h (post relu)
__device__ int   g_idx64;               // 1 if edge_index is int64, 0 if int32

// ----------------------------------------------------------------------------
// edge_index dtype detection: reference asks for int64 but default JAX config
// downcasts to int32. If the buffer really holds int64 node ids, every 8-byte
// word is in [0, NN). If it holds int32, the int64 view combines two random
// ids -> almost surely >= NN. 64 samples => error prob ~ (1e-5)^64.
// ----------------------------------------------------------------------------
__global__ void k_detect_idx(const void* ei) {
    const long long* p = (const long long*)ei;
    int is64 = 1;
    for (int i = 0; i < 64; i++) {
        long long v = p[i];
        if (v < 0 || v >= NN) { is64 = 0; break; }
    }
    g_idx64 = is64;
}

__device__ __forceinline__ int edge_at(const void* ei, long long i) {
    if (g_idx64) return (int)((const long long*)ei)[i];
    return ((const int*)ei)[i];
}

// ----------------------------------------------------------------------------
// Degree / norm
// ----------------------------------------------------------------------------
__global__ void k_init_deg() {
    int i = blockIdx.x * blockDim.x + threadIdx.x;
    if (i < NN) g_dinv[i] = 1.0f;           // self-loop
}

__global__ void k_count_deg(const void* ei) {
    int e = blockIdx.x * blockDim.x + threadIdx.x;
    if (e < EE) {
        int d = edge_at(ei, (long long)EE + e);   // dst row
        atomicAdd(&g_dinv[d], 1.0f);
    }
}

__global__ void k_dinv() {
    int i = blockIdx.x * blockDim.x + threadIdx.x;
    if (i < NN) g_dinv[i] = rsqrtf(g_dinv[i]);    // deg >= 1 always
}

__global__ void k_norm(const void* ei) {
    int e = blockIdx.x * blockDim.x + threadIdx.x;
    if (e < EE) {
        int s = edge_at(ei, e);
        int d = edge_at(ei, (long long)EE + e);
        g_norm[e] = g_dinv[s] * g_dinv[d];
    }
}

// ----------------------------------------------------------------------------
// GEMM1: t = x @ W1     [NN,256] x [256,64]
// block = 128 threads, one row per thread, W staged through smem in 64-k chunks
// ----------------------------------------------------------------------------
__global__ void k_gemm1(const float* __restrict__ x, const float* __restrict__ W1) {
    __shared__ float4 sW[64 * 16];   // [k][c4], 16 KB
    int row = blockIdx.x * 128 + threadIdx.x;
    float acc[64];
#pragma unroll
    for (int c = 0; c < 64; c++) acc[c] = 0.0f;

    for (int k0 = 0; k0 < IN_F; k0 += 64) {
        __syncthreads();
        const float4* Wv = (const float4*)(W1 + (long long)k0 * 64);
#pragma unroll
        for (int j = 0; j < 8; j++) sW[threadIdx.x + j * 128] = Wv[threadIdx.x + j * 128];
        __syncthreads();

        if (row < NN) {
            const float* xr = x + (long long)row * IN_F + k0;
#pragma unroll 4
            for (int k = 0; k < 64; k++) {
                float xv = __ldg(&xr[k]);
#pragma unroll
                for (int c4 = 0; c4 < 16; c4++) {
                    float4 w = sW[k * 16 + c4];
                    acc[c4 * 4 + 0] += xv * w.x;
                    acc[c4 * 4 + 1] += xv * w.y;
                    acc[c4 * 4 + 2] += xv * w.z;
                    acc[c4 * 4 + 3] += xv * w.w;
                }
            }
        }
    }
    if (row < NN) {
        float4* o = (float4*)(g_t + (long long)row * 64);
#pragma unroll
        for (int c4 = 0; c4 < 16; c4++)
            o[c4] = make_float4(acc[c4 * 4 + 0], acc[c4 * 4 + 1], acc[c4 * 4 + 2], acc[c4 * 4 + 3]);
    }
}

// ----------------------------------------------------------------------------
// GEMM2: t = h @ [Wmu | Wlv]   [NN,64] x [64,64]   (h lives in g_agg)
// ----------------------------------------------------------------------------
__global__ void k_gemm2(const float* __restrict__ Wmu, const float* __restrict__ Wlv) {
    __shared__ float sW[64 * 64];    // 16 KB, [k][c]
    int row = blockIdx.x * 128 + threadIdx.x;

    for (int j = threadIdx.x; j < 64 * 32; j += 128) {
        int k = j / 32, c = j % 32;
        sW[k * 64 + c]      = Wmu[j];
        sW[k * 64 + 32 + c] = Wlv[j];
    }
    __syncthreads();

    float acc[64];
#pragma unroll
    for (int c = 0; c < 64; c++) acc[c] = 0.0f;

    if (row < NN) {
        const float* hr = g_agg + (long long)row * 64;
        const float4* sW4 = (const float4*)sW;
#pragma unroll 4
        for (int k = 0; k < 64; k++) {
            float hv = hr[k];
#pragma unroll
            for (int c4 = 0; c4 < 16; c4++) {
                float4 w = sW4[k * 16 + c4];
                acc[c4 * 4 + 0] += hv * w.x;
                acc[c4 * 4 + 1] += hv * w.y;
                acc[c4 * 4 + 2] += hv * w.z;
                acc[c4 * 4 + 3] += hv * w.w;
            }
        }
        float4* o = (float4*)(g_t + (long long)row * 64);
#pragma unroll
        for (int c4 = 0; c4 < 16; c4++)
            o[c4] = make_float4(acc[c4 * 4 + 0], acc[c4 * 4 + 1], acc[c4 * 4 + 2], acc[c4 * 4 + 3]);
    }
}

// ----------------------------------------------------------------------------
// Layer-1 aggregation
// ----------------------------------------------------------------------------
__global__ void k_agg1_init() {
    int i = blockIdx.x * blockDim.x + threadIdx.x;
    if (i < NN * HID_F) {
        int n = i >> 6;
        float dv = g_dinv[n];
        g_agg[i] = g_t[i] * dv * dv;      // self-loop contribution
    }
}

__global__ void k_edge_agg1(const void* ei) {
    int t = blockIdx.x * blockDim.x + threadIdx.x;
    if (t >= EE * HID_F) return;
    int e = t >> 6;
    int f = t & 63;
    int s = edge_at(ei, e);
    int d = edge_at(ei, (long long)EE + e);
    float nv = g_norm[e];
    atomicAdd(&g_agg[(long long)d * 64 + f], g_t[(long long)s * 64 + f] * nv);
}

__global__ void k_relu_bias(const float* __restrict__ b1) {
    int i = blockIdx.x * blockDim.x + threadIdx.x;
    if (i < NN * HID_F) {
        g_agg[i] = fmaxf(g_agg[i] + b1[i & 63], 0.0f);   // in-place: g_agg becomes h
    }
}

// ----------------------------------------------------------------------------
// Layer-2 aggregation directly into d_out (mu then logvar)
// ----------------------------------------------------------------------------
__global__ void k_out_init(float* __restrict__ out,
                           const float* __restrict__ bmu, const float* __restrict__ blv) {
    int i = blockIdx.x * blockDim.x + threadIdx.x;
    if (i < NN * HID_F) {
        int n = i >> 6;
        int f = i & 63;
        float dv = g_dinv[n];
        float v = g_t[i] * dv * dv;
        if (f < 32) out[(long long)n * 32 + f]               = v + bmu[f];
        else        out[(long long)NN * 32 + (long long)n * 32 + (f - 32)] = v + blv[f - 32];
    }
}

__global__ void k_edge_agg2(const void* ei, float* __restrict__ out) {
    int t = blockIdx.x * blockDim.x + threadIdx.x;
    if (t >= EE * HID_F) return;
    int e = t >> 6;
    int f = t & 63;
    int s = edge_at(ei, e);
    int d = edge_at(ei, (long long)EE + e);
    float v = g_t[(long long)s * 64 + f] * g_norm[e];
    if (f < 32) atomicAdd(&out[(long long)d * 32 + f], v);
    else        atomicAdd(&out[(long long)NN * 32 + (long long)d * 32 + (f - 32)], v);
}

// ----------------------------------------------------------------------------
// Launch
// ----------------------------------------------------------------------------
extern "C" void kernel_launch(void* const* d_in, const int* in_sizes, int n_in,
                              void* d_out, int out_size) {
    const float* x   = (const float*)d_in[0];
    const void*  ei  = d_in[1];             // int64 or int32, detected on device
    const float* W1  = (const float*)d_in[2];
    const float* b1  = (const float*)d_in[3];
    const float* Wmu = (const float*)d_in[4];
    const float* bmu = (const float*)d_in[5];
    const float* Wlv = (const float*)d_in[6];
    const float* blv = (const float*)d_in[7];
    float* out = (float*)d_out;

    const int T = 256;
    const int gN  = (NN + T - 1) / T;
    const int gE  = (EE + T - 1) / T;
    const int gNF = (NN * HID_F + T - 1) / T;
    const long long ef = (long long)EE * HID_F;
    const int gEF = (int)((ef + T - 1) / T);

    k_detect_idx<<<1, 1>>>(ei);
    k_init_deg<<<gN, T>>>();
    k_count_deg<<<gE, T>>>(ei);
    k_dinv<<<gN, T>>>();
    k_norm<<<gE, T>>>(ei);

    k_gemm1<<<(NN + 127) / 128, 128>>>(x, W1);
    k_agg1_init<<<gNF, T>>>();
    k_edge_agg1<<<gEF, T>>>(ei);
    k_relu_bias<<<gNF, T>>>(b1);

    k_gemm2<<<(NN + 127) / 128, 128>>>(Wmu, Wlv);
    k_out_init<<<gNF, T>>>(out, bmu, blv);
    k_edge_agg2<<<gEF, T>>>(ei, out);
}

// round 2
// speedup vs baseline: 2.4532x; 2.4532x over previous
#include <cuda_runtime.h>

// Problem shape (fixed by the dataset)
#define NN    100000
#define EE    1600000
#define IN_F  256
#define HID_F 64
#define OUT_F 32

#define SCAN_B   1024
#define SCAN_NB  ((NN + SCAN_B - 1) / SCAN_B)   // 98

// ----------------------------------------------------------------------------
// Scratch (__device__ globals; no dynamic allocation allowed)
// ----------------------------------------------------------------------------
__device__ float g_dinv[NN];          // rsqrt(1 + in-degree)
__device__ int   g_cnt[NN];           // in-degree histogram
__device__ int   g_rowptr[NN + 1];    // CSR row pointers (by dst)
__device__ int   g_cur[NN];           // scatter cursors
__device__ int   g_bsum[SCAN_NB];     // block sums for scan
__device__ int2  g_csr[EE];           // {src, __float_as_int(norm)} per edge, CSR order
__device__ float g_t[NN * HID_F];     // x@W1, later h@[Wmu|Wlv]
__device__ float g_agg[NN * HID_F];   // h after layer-1 (bias+relu applied)
__device__ int   g_idx64;             // 1 if edge_index is int64, 0 if int32

// ----------------------------------------------------------------------------
// edge_index dtype detection (reference asks int64; JAX may deliver int32)
// ----------------------------------------------------------------------------
__global__ void k_detect_idx(const void* ei) {
    const long long* p = (const long long*)ei;
    int is64 = 1;
    for (int i = 0; i < 64; i++) {
        long long v = p[i];
        if (v < 0 || v >= NN) { is64 = 0; break; }
    }
    g_idx64 = is64;
}

__device__ __forceinline__ int edge_at(const void* ei, long long i) {
    if (g_idx64) return (int)((const long long*)ei)[i];
    return ((const int*)ei)[i];
}

// ----------------------------------------------------------------------------
// CSR build: histogram -> exclusive scan -> scatter (with per-edge norm)
// ----------------------------------------------------------------------------
__global__ void k_zero_cnt() {
    int i = blockIdx.x * blockDim.x + threadIdx.x;
    if (i < NN) g_cnt[i] = 0;
}

__global__ void k_hist(const void* ei) {
    int e = blockIdx.x * blockDim.x + threadIdx.x;
    if (e < EE) atomicAdd(&g_cnt[edge_at(ei, (long long)EE + e)], 1);
}

__global__ void k_dinv_from_cnt() {
    int i = blockIdx.x * blockDim.x + threadIdx.x;
    if (i < NN) g_dinv[i] = rsqrtf((float)(1 + g_cnt[i]));   // +1 self-loop
}

// exclusive scan, stage 1: per-block Hillis-Steele
__global__ void k_scan1() {
    __shared__ int sh[SCAN_B];
    int tid = threadIdx.x;
    int i = blockIdx.x * SCAN_B + tid;
    int v = (i < NN) ? g_cnt[i] : 0;
    sh[tid] = v;
    __syncthreads();
    for (int off = 1; off < SCAN_B; off <<= 1) {
        int t = 0;
        if (tid >= off) t = sh[tid - off];
        __syncthreads();
        if (tid >= off) sh[tid] += t;
        __syncthreads();
    }
    if (i < NN) g_rowptr[i] = sh[tid] - v;          // exclusive
    if (tid == SCAN_B - 1) g_bsum[blockIdx.x] = sh[tid];
}

// stage 2: serial scan of 98 block sums (single thread; trivial cost)
__global__ void k_scan2() {
    if (threadIdx.x == 0) {
        int acc = 0;
        for (int b = 0; b < SCAN_NB; b++) {
            int v = g_bsum[b];
            g_bsum[b] = acc;
            acc += v;
        }
        g_rowptr[NN] = EE;
    }
}

// stage 3: add block offsets, init cursors
__global__ void k_scan3() {
    int i = blockIdx.x * SCAN_B + threadIdx.x;
    if (i < NN) {
        int r = g_rowptr[i] + g_bsum[blockIdx.x];
        g_rowptr[i] = r;
        g_cur[i] = r;
    }
}

__global__ void k_scatter(const void* ei) {
    int e = blockIdx.x * blockDim.x + threadIdx.x;
    if (e < EE) {
        int s = edge_at(ei, e);
        int d = edge_at(ei, (long long)EE + e);
        int pos = atomicAdd(&g_cur[d], 1);
        float nv = g_dinv[s] * g_dinv[d];
        g_csr[pos] = make_int2(s, __float_as_int(nv));
    }
}

// ----------------------------------------------------------------------------
// GEMM1: t = x @ W1     [NN,256] x [256,64]
// ----------------------------------------------------------------------------
__global__ void k_gemm1(const float* __restrict__ x, const float* __restrict__ W1) {
    __shared__ float4 sW[64 * 16];   // [k][c4], 16 KB
    int row = blockIdx.x * 128 + threadIdx.x;
    float acc[64];
#pragma unroll
    for (int c = 0; c < 64; c++) acc[c] = 0.0f;

    for (int k0 = 0; k0 < IN_F; k0 += 64) {
        __syncthreads();
        const float4* Wv = (const float4*)(W1 + (long long)k0 * 64);
#pragma unroll
        for (int j = 0; j < 8; j++) sW[threadIdx.x + j * 128] = Wv[threadIdx.x + j * 128];
        __syncthreads();

        if (row < NN) {
            const float* xr = x + (long long)row * IN_F + k0;
#pragma unroll 4
            for (int k = 0; k < 64; k++) {
                float xv = __ldg(&xr[k]);
#pragma unroll
                for (int c4 = 0; c4 < 16; c4++) {
                    float4 w = sW[k * 16 + c4];
                    acc[c4 * 4 + 0] += xv * w.x;
                    acc[c4 * 4 + 1] += xv * w.y;
                    acc[c4 * 4 + 2] += xv * w.z;
                    acc[c4 * 4 + 3] += xv * w.w;
                }
            }
        }
    }
    if (row < NN) {
        float4* o = (float4*)(g_t + (long long)row * 64);
#pragma unroll
        for (int c4 = 0; c4 < 16; c4++)
            o[c4] = make_float4(acc[c4 * 4 + 0], acc[c4 * 4 + 1], acc[c4 * 4 + 2], acc[c4 * 4 + 3]);
    }
}

// ----------------------------------------------------------------------------
// GEMM2: t = h @ [Wmu | Wlv]   [NN,64] x [64,64]   (h lives in g_agg)
// ----------------------------------------------------------------------------
__global__ void k_gemm2(const float* __restrict__ Wmu, const float* __restrict__ Wlv) {
    __shared__ float sW[64 * 64];    // 16 KB, [k][c]
    int row = blockIdx.x * 128 + threadIdx.x;

    for (int j = threadIdx.x; j < 64 * 32; j += 128) {
        int k = j / 32, c = j % 32;
        sW[k * 64 + c]      = Wmu[j];
        sW[k * 64 + 32 + c] = Wlv[j];
    }
    __syncthreads();

    float acc[64];
#pragma unroll
    for (int c = 0; c < 64; c++) acc[c] = 0.0f;

    if (row < NN) {
        const float* hr = g_agg + (long long)row * 64;
        const float4* sW4 = (const float4*)sW;
#pragma unroll 4
        for (int k = 0; k < 64; k++) {
            float hv = hr[k];
#pragma unroll
            for (int c4 = 0; c4 < 16; c4++) {
                float4 w = sW4[k * 16 + c4];
                acc[c4 * 4 + 0] += hv * w.x;
                acc[c4 * 4 + 1] += hv * w.y;
                acc[c4 * 4 + 2] += hv * w.z;
                acc[c4 * 4 + 3] += hv * w.w;
            }
        }
        float4* o = (float4*)(g_t + (long long)row * 64);
#pragma unroll
        for (int c4 = 0; c4 < 16; c4++)
            o[c4] = make_float4(acc[c4 * 4 + 0], acc[c4 * 4 + 1], acc[c4 * 4 + 2], acc[c4 * 4 + 3]);
    }
}

// ----------------------------------------------------------------------------
// CSR segment-sum aggregation: one warp per node, float2 per lane (64 feats)
// ----------------------------------------------------------------------------
__global__ void k_agg1(const float* __restrict__ b1) {
    int warp = (blockIdx.x * blockDim.x + threadIdx.x) >> 5;
    int lane = threadIdx.x & 31;
    if (warp >= NN) return;

    const float2* t2 = (const float2*)g_t;
    float dv = g_dinv[warp];
    float2 self = t2[(long long)warp * 32 + lane];
    float2 acc = make_float2(self.x * dv * dv, self.y * dv * dv);

    int beg = g_rowptr[warp], end = g_rowptr[warp + 1];
    for (int base = beg; base < end; base += 32) {
        int n = min(32, end - base);
        int2 e = make_int2(0, 0);
        if (lane < n) e = g_csr[base + lane];
        for (int j = 0; j < n; j++) {
            int   sj = __shfl_sync(0xffffffffu, e.x, j);
            float nj = __int_as_float(__shfl_sync(0xffffffffu, e.y, j));
            float2 v = t2[(long long)sj * 32 + lane];
            acc.x += v.x * nj;
            acc.y += v.y * nj;
        }
    }
    float bx = b1[lane * 2], by = b1[lane * 2 + 1];
    float2 r = make_float2(fmaxf(acc.x + bx, 0.0f), fmaxf(acc.y + by, 0.0f));
    ((float2*)g_agg)[(long long)warp * 32 + lane] = r;
}

__global__ void k_agg2(const float* __restrict__ bmu, const float* __restrict__ blv,
                       float* __restrict__ out) {
    int warp = (blockIdx.x * blockDim.x + threadIdx.x) >> 5;
    int lane = threadIdx.x & 31;
    if (warp >= NN) return;

    const float2* t2 = (const float2*)g_t;
    float dv = g_dinv[warp];
    float2 self = t2[(long long)warp * 32 + lane];
    float2 acc = make_float2(self.x * dv * dv, self.y * dv * dv);

    int beg = g_rowptr[warp], end = g_rowptr[warp + 1];
    for (int base = beg; base < end; base += 32) {
        int n = min(32, end - base);
        int2 e = make_int2(0, 0);
        if (lane < n) e = g_csr[base + lane];
        for (int j = 0; j < n; j++) {
            int   sj = __shfl_sync(0xffffffffu, e.x, j);
            float nj = __int_as_float(__shfl_sync(0xffffffffu, e.y, j));
            float2 v = t2[(long long)sj * 32 + lane];
            acc.x += v.x * nj;
            acc.y += v.y * nj;
        }
    }
    // features lane*2, lane*2+1: lanes 0..15 -> mu[0..31], lanes 16..31 -> logvar[0..31]
    float2* out2 = (float2*)out;
    if (lane < 16) {
        float2 r = make_float2(acc.x + bmu[lane * 2], acc.y + bmu[lane * 2 + 1]);
        out2[(long long)warp * 16 + lane] = r;
    } else {
        int l = lane - 16;
        float2 r = make_float2(acc.x + blv[l * 2], acc.y + blv[l * 2 + 1]);
        out2[(long long)NN * 16 + (long long)warp * 16 + l] = r;
    }
}

// ----------------------------------------------------------------------------
// Launch
// ----------------------------------------------------------------------------
extern "C" void kernel_launch(void* const* d_in, const int* in_sizes, int n_in,
                              void* d_out, int out_size) {
    const float* x   = (const float*)d_in[0];
    const void*  ei  = d_in[1];
    const float* W1  = (const float*)d_in[2];
    const float* b1  = (const float*)d_in[3];
    const float* Wmu = (const float*)d_in[4];
    const float* bmu = (const float*)d_in[5];
    const float* Wlv = (const float*)d_in[6];
    const float* blv = (const float*)d_in[7];
    float* out = (float*)d_out;

    const int T = 256;
    const int gN = (NN + T - 1) / T;
    const int gE = (EE + T - 1) / T;
    const int gW = (NN * 32 + T - 1) / T;   // warp-per-node kernels (8 warps/block)

    // CSR build (runs inside the graph every replay; deterministic work)
    k_detect_idx<<<1, 1>>>(ei);
    k_zero_cnt<<<gN, T>>>();
    k_hist<<<gE, T>>>(ei);
    k_dinv_from_cnt<<<gN, T>>>();
    k_scan1<<<SCAN_NB, SCAN_B>>>();
    k_scan2<<<1, 32>>>();
    k_scan3<<<SCAN_NB, SCAN_B>>>();
    k_scatter<<<gE, T>>>(ei);

    // Layer 1
    k_gemm1<<<(NN + 127) / 128, 128>>>(x, W1);
    k_agg1<<<gW, T>>>(b1);

    // Layer 2
    k_gemm2<<<(NN + 127) / 128, 128>>>(Wmu, Wlv);
    k_agg2<<<gW, T>>>(bmu, blv, out);
}

// round 5
// speedup vs baseline: 4.4821x; 1.8270x over previous
#include <cuda_runtime.h>

// Problem shape (fixed by the dataset)
#define NN    100000
#define EE    1600000
#define IN_F  256
#define HID_F 64
#define OUT_F 32

#define SCAN_B   1024
#define SCAN_NB  ((NN + SCAN_B - 1) / SCAN_B)   // 98

// ----------------------------------------------------------------------------
// Scratch (__device__ globals; no dynamic allocation allowed)
// ----------------------------------------------------------------------------
__device__ float g_dinv[NN];          // rsqrt(1 + in-degree)
__device__ int   g_cnt[NN];           // in-degree histogram
__device__ int   g_rowptr[NN + 1];    // CSR row pointers (by dst)
__device__ int   g_cur[NN];           // scatter cursors
__device__ int   g_bsum[SCAN_NB];     // block sums for scan
__device__ int2  g_csr[EE];           // {src, __float_as_int(norm)}, CSR order
__device__ float g_t[NN * HID_F];     // x@W1, later h@[Wmu|Wlv]
__device__ float g_agg[NN * HID_F];   // h after layer-1 (bias+relu applied)
__device__ int   g_idx64;             // 1 if edge_index is int64, 0 if int32

__device__ __forceinline__ int edge_at(const void* ei, long long i) {
    if (g_idx64) return (int)((const long long*)ei)[i];
    return ((const int*)ei)[i];
}

// ----------------------------------------------------------------------------
// Fused: zero histogram + parallel dtype detection (warp ballot)
// ----------------------------------------------------------------------------
__global__ void k_detect_zero(const void* ei) {
    int i = blockIdx.x * blockDim.x + threadIdx.x;
    if (i < NN) g_cnt[i] = 0;
    if (blockIdx.x == 0 && threadIdx.x < 32) {
        const long long* p = (const long long*)ei;
        bool ok = true;
#pragma unroll
        for (int j = 0; j < 2; j++) {
            long long v = p[threadIdx.x + j * 32];
            if (v < 0 || v >= NN) ok = false;
        }
        unsigned m = __ballot_sync(0xffffffffu, ok);
        if (threadIdx.x == 0) g_idx64 = (m == 0xffffffffu) ? 1 : 0;
    }
}

__global__ void k_hist(const void* ei) {
    int e = blockIdx.x * blockDim.x + threadIdx.x;
    if (e < EE) atomicAdd(&g_cnt[edge_at(ei, (long long)EE + e)], 1);
}

// ----------------------------------------------------------------------------
// Exclusive scan of g_cnt -> g_rowptr, dinv fused in stage 1
// ----------------------------------------------------------------------------
__global__ void k_scan1() {
    __shared__ int sh[SCAN_B];
    int tid = threadIdx.x;
    int i = blockIdx.x * SCAN_B + tid;
    int v = (i < NN) ? g_cnt[i] : 0;
    if (i < NN) g_dinv[i] = rsqrtf((float)(1 + v));   // +1 self-loop
    sh[tid] = v;
    __syncthreads();
    for (int off = 1; off < SCAN_B; off <<= 1) {
        int t = 0;
        if (tid >= off) t = sh[tid - off];
        __syncthreads();
        if (tid >= off) sh[tid] += t;
        __syncthreads();
    }
    if (i < NN) g_rowptr[i] = sh[tid] - v;            // exclusive
    if (tid == SCAN_B - 1) g_bsum[blockIdx.x] = sh[tid];
}

// stage 2: parallel scan of 98 block sums in a single 128-thread block
__global__ void k_scan2() {
    __shared__ int wsum[4];
    int t = threadIdx.x;                 // 0..127
    int lane = t & 31, warp = t >> 5;
    int v = (t < SCAN_NB) ? g_bsum[t] : 0;
    int incl = v;
#pragma unroll
    for (int off = 1; off < 32; off <<= 1) {
        int u = __shfl_up_sync(0xffffffffu, incl, off);
        if (lane >= off) incl += u;
    }
    if (lane == 31) wsum[warp] = incl;
    __syncthreads();
    if (warp == 0 && lane < 4) {
        int w = wsum[lane];
#pragma unroll
        for (int off = 1; off < 4; off <<= 1) {
            int u = __shfl_up_sync(0x0000000fu, w, off);
            if (lane >= off) w += u;
        }
        wsum[lane] = w;
    }
    __syncthreads();
    int base = (warp > 0) ? wsum[warp - 1] : 0;
    if (t < SCAN_NB) g_bsum[t] = base + incl - v;    // exclusive
    if (t == 0) g_rowptr[NN] = EE;
}

// stage 3: add block offsets, init cursors
__global__ void k_scan3() {
    int i = blockIdx.x * SCAN_B + threadIdx.x;
    if (i < NN) {
        int r = g_rowptr[i] + g_bsum[blockIdx.x];
        g_rowptr[i] = r;
        g_cur[i] = r;
    }
}

__global__ void k_scatter(const void* ei) {
    int e = blockIdx.x * blockDim.x + threadIdx.x;
    if (e < EE) {
        int s = edge_at(ei, e);
        int d = edge_at(ei, (long long)EE + e);
        int pos = atomicAdd(&g_cur[d], 1);
        float nv = g_dinv[s] * g_dinv[d];
        g_csr[pos] = make_int2(s, __float_as_int(nv));
    }
}

// ----------------------------------------------------------------------------
// tf32 tensor-core GEMM helpers
// ----------------------------------------------------------------------------
__device__ __forceinline__ unsigned f2tf32(float f) {
    unsigned r;
    asm("cvt.rna.tf32.f32 %0, %1;" : "=r"(r) : "f"(f));
    return r;
}

__device__ __forceinline__ void mma_tf32(float* d, const unsigned* a, const unsigned* b) {
    asm volatile(
        "mma.sync.aligned.m16n8k8.row.col.f32.tf32.tf32.f32 "
        "{%0,%1,%2,%3}, {%4,%5,%6,%7}, {%8,%9}, {%0,%1,%2,%3};\n"
        : "+f"(d[0]), "+f"(d[1]), "+f"(d[2]), "+f"(d[3])
        : "r"(a[0]), "r"(a[1]), "r"(a[2]), "r"(a[3]), "r"(b[0]), "r"(b[1]));
}

// ----------------------------------------------------------------------------
// GEMM1: g_t = x @ W1   [NN,256]x[256,64], tf32 mma, BM=64 per block (4 warps)
// ----------------------------------------------------------------------------
__global__ void k_gemm1(const float* __restrict__ x, const float* __restrict__ W1) {
    __shared__ float sx[64][36];   // x tile (tf32 bits), row-major [m][k]
    __shared__ float sw[64][36];   // W chunk transposed [n][k]
    int tid = threadIdx.x;
    int warp = tid >> 5, lane = tid & 31;
    int g = lane >> 2, tg = lane & 3;
    long long bm0 = (long long)blockIdx.x * 64;

    float acc[8][4];
#pragma unroll
    for (int nt = 0; nt < 8; nt++)
#pragma unroll
        for (int q = 0; q < 4; q++) acc[nt][q] = 0.0f;

    for (int k0 = 0; k0 < IN_F; k0 += 32) {
        __syncthreads();
        // x tile: 64 rows x 32 cols = 512 float4
#pragma unroll
        for (int j = 0; j < 4; j++) {
            int idx = tid + j * 128;
            int r = idx >> 3, c4 = idx & 7;
            long long row = bm0 + r;
            float4 v = make_float4(0.f, 0.f, 0.f, 0.f);
            if (row < NN) v = *(const float4*)(x + row * IN_F + k0 + c4 * 4);
            float4 c = make_float4(__uint_as_float(f2tf32(v.x)), __uint_as_float(f2tf32(v.y)),
                                   __uint_as_float(f2tf32(v.z)), __uint_as_float(f2tf32(v.w)));
            *(float4*)&sx[r][c4 * 4] = c;
        }
        // W chunk: rows k0..k0+31 of [256][64], stored transposed [n][k]
#pragma unroll
        for (int j = 0; j < 4; j++) {
            int idx = tid + j * 128;
            int kr = idx >> 4, c4 = idx & 15;
            float4 v = *(const float4*)(W1 + (long long)(k0 + kr) * 64 + c4 * 4);
            sw[c4 * 4 + 0][kr] = __uint_as_float(f2tf32(v.x));
            sw[c4 * 4 + 1][kr] = __uint_as_float(f2tf32(v.y));
            sw[c4 * 4 + 2][kr] = __uint_as_float(f2tf32(v.z));
            sw[c4 * 4 + 3][kr] = __uint_as_float(f2tf32(v.w));
        }
        __syncthreads();
#pragma unroll
        for (int kk = 0; kk < 32; kk += 8) {
            unsigned a[4];
            a[0] = __float_as_uint(sx[warp * 16 + g][kk + tg]);
            a[1] = __float_as_uint(sx[warp * 16 + g + 8][kk + tg]);
            a[2] = __float_as_uint(sx[warp * 16 + g][kk + tg + 4]);
            a[3] = __float_as_uint(sx[warp * 16 + g + 8][kk + tg + 4]);
#pragma unroll
            for (int nt = 0; nt < 8; nt++) {
                unsigned b[2];
                b[0] = __float_as_uint(sw[nt * 8 + g][kk + tg]);
                b[1] = __float_as_uint(sw[nt * 8 + g][kk + tg + 4]);
                mma_tf32(acc[nt], a, b);
            }
        }
    }
    long long r0 = bm0 + warp * 16 + g;
#pragma unroll
    for (int nt = 0; nt < 8; nt++) {
        int col = nt * 8 + tg * 2;
        if (r0 < NN)     *(float2*)&g_t[r0 * 64 + col]       = make_float2(acc[nt][0], acc[nt][1]);
        if (r0 + 8 < NN) *(float2*)&g_t[(r0 + 8) * 64 + col] = make_float2(acc[nt][2], acc[nt][3]);
    }
}

// ----------------------------------------------------------------------------
// GEMM2: g_t = h @ [Wmu|Wlv]   [NN,64]x[64,64], tf32 mma (h in g_agg)
// ----------------------------------------------------------------------------
__global__ void k_gemm2(const float* __restrict__ Wmu, const float* __restrict__ Wlv) {
    __shared__ float sx[64][36];
    __shared__ float sw[64][36];   // [n][k]
    int tid = threadIdx.x;
    int warp = tid >> 5, lane = tid & 31;
    int g = lane >> 2, tg = lane & 3;
    long long bm0 = (long long)blockIdx.x * 64;

    float acc[8][4];
#pragma unroll
    for (int nt = 0; nt < 8; nt++)
#pragma unroll
        for (int q = 0; q < 4; q++) acc[nt][q] = 0.0f;

    for (int k0 = 0; k0 < HID_F; k0 += 32) {
        __syncthreads();
#pragma unroll
        for (int j = 0; j < 4; j++) {
            int idx = tid + j * 128;
            int r = idx >> 3, c4 = idx & 7;
            long long row = bm0 + r;
            float4 v = make_float4(0.f, 0.f, 0.f, 0.f);
            if (row < NN) v = *(const float4*)(g_agg + row * HID_F + k0 + c4 * 4);
            float4 c = make_float4(__uint_as_float(f2tf32(v.x)), __uint_as_float(f2tf32(v.y)),
                                   __uint_as_float(f2tf32(v.z)), __uint_as_float(f2tf32(v.w)));
            *(float4*)&sx[r][c4 * 4] = c;
        }
        // combined weight chunk: cols 0..31 = Wmu[:,0..31], cols 32..63 = Wlv
#pragma unroll
        for (int j = 0; j < 4; j++) {
            int idx = tid + j * 128;
            int kr = idx >> 4, c4 = idx & 15;
            const float* Wsrc = (c4 < 8) ? Wmu : Wlv;
            int cc4 = (c4 < 8) ? c4 : (c4 - 8);
            float4 v = *(const float4*)(Wsrc + (long long)(k0 + kr) * 32 + cc4 * 4);
            sw[c4 * 4 + 0][kr] = __uint_as_float(f2tf32(v.x));
            sw[c4 * 4 + 1][kr] = __uint_as_float(f2tf32(v.y));
            sw[c4 * 4 + 2][kr] = __uint_as_float(f2tf32(v.z));
            sw[c4 * 4 + 3][kr] = __uint_as_float(f2tf32(v.w));
        }
        __syncthreads();
#pragma unroll
        for (int kk = 0; kk < 32; kk += 8) {
            unsigned a[4];
            a[0] = __float_as_uint(sx[warp * 16 + g][kk + tg]);
            a[1] = __float_as_uint(sx[warp * 16 + g + 8][kk + tg]);
            a[2] = __float_as_uint(sx[warp * 16 + g][kk + tg + 4]);
            a[3] = __float_as_uint(sx[warp * 16 + g + 8][kk + tg + 4]);
#pragma unroll
            for (int nt = 0; nt < 8; nt++) {
                unsigned b[2];
                b[0] = __float_as_uint(sw[nt * 8 + g][kk + tg]);
                b[1] = __float_as_uint(sw[nt * 8 + g][kk + tg + 4]);
                mma_tf32(acc[nt], a, b);
            }
        }
    }
    long long r0 = bm0 + warp * 16 + g;
#pragma unroll
    for (int nt = 0; nt < 8; nt++) {
        int col = nt * 8 + tg * 2;
        if (r0 < NN)     *(float2*)&g_t[r0 * 64 + col]       = make_float2(acc[nt][0], acc[nt][1]);
        if (r0 + 8 < NN) *(float2*)&g_t[(r0 + 8) * 64 + col] = make_float2(acc[nt][2], acc[nt][3]);
    }
}

// ----------------------------------------------------------------------------
// CSR segment-sum aggregation: one warp per node, float2 per lane (64 feats)
// ----------------------------------------------------------------------------
__global__ void k_agg1(const float* __restrict__ b1) {
    int warp = (blockIdx.x * blockDim.x + threadIdx.x) >> 5;
    int lane = threadIdx.x & 31;
    if (warp >= NN) return;

    const float2* t2 = (const float2*)g_t;
    float dv = g_dinv[warp];
    float2 self = t2[(long long)warp * 32 + lane];
    float2 acc = make_float2(self.x * dv * dv, self.y * dv * dv);

    int beg = g_rowptr[warp], end = g_rowptr[warp + 1];
    for (int base = beg; base < end; base += 32) {
        int n = min(32, end - base);
        int2 e = make_int2(0, 0);
        if (lane < n) e = g_csr[base + lane];
        for (int j = 0; j < n; j++) {
            int   sj = __shfl_sync(0xffffffffu, e.x, j);
            float nj = __int_as_float(__shfl_sync(0xffffffffu, e.y, j));
            float2 v = t2[(long long)sj * 32 + lane];
            acc.x += v.x * nj;
            acc.y += v.y * nj;
        }
    }
    float bx = b1[lane * 2], by = b1[lane * 2 + 1];
    float2 r = make_float2(fmaxf(acc.x + bx, 0.0f), fmaxf(acc.y + by, 0.0f));
    ((float2*)g_agg)[(long long)warp * 32 + lane] = r;
}

__global__ void k_agg2(const float* __restrict__ bmu, const float* __restrict__ blv,
                       float* __restrict__ out) {
    int warp = (blockIdx.x * blockDim.x + threadIdx.x) >> 5;
    int lane = threadIdx.x & 31;
    if (warp >= NN) return;

    const float2* t2 = (const float2*)g_t;
    float dv = g_dinv[warp];
    float2 self = t2[(long long)warp * 32 + lane];
    float2 acc = make_float2(self.x * dv * dv, self.y * dv * dv);

    int beg = g_rowptr[warp], end = g_rowptr[warp + 1];
    for (int base = beg; base < end; base += 32) {
        int n = min(32, end - base);
        int2 e = make_int2(0, 0);
        if (lane < n) e = g_csr[base + lane];
        for (int j = 0; j < n; j++) {
            int   sj = __shfl_sync(0xffffffffu, e.x, j);
            float nj = __int_as_float(__shfl_sync(0xffffffffu, e.y, j));
            float2 v = t2[(long long)sj * 32 + lane];
            acc.x += v.x * nj;
            acc.y += v.y * nj;
        }
    }
    float2* out2 = (float2*)out;
    if (lane < 16) {
        float2 r = make_float2(acc.x + bmu[lane * 2], acc.y + bmu[lane * 2 + 1]);
        out2[(long long)warp * 16 + lane] = r;
    } else {
        int l = lane - 16;
        float2 r = make_float2(acc.x + blv[l * 2], acc.y + blv[l * 2 + 1]);
        out2[(long long)NN * 16 + (long long)warp * 16 + l] = r;
    }
}

// ----------------------------------------------------------------------------
// Launch
// ----------------------------------------------------------------------------
extern "C" void kernel_launch(void* const* d_in, const int* in_sizes, int n_in,
                              void* d_out, int out_size) {
    const float* x   = (const float*)d_in[0];
    const void*  ei  = d_in[1];
    const float* W1  = (const float*)d_in[2];
    const float* b1  = (const float*)d_in[3];
    const float* Wmu = (const float*)d_in[4];
    const float* bmu = (const float*)d_in[5];
    const float* Wlv = (const float*)d_in[6];
    const float* blv = (const float*)d_in[7];
    float* out = (float*)d_out;

    const int T = 256;
    const int gN = (NN + T - 1) / T;
    const int gE = (EE + T - 1) / T;
    const int gW = (NN * 32 + T - 1) / T;     // warp-per-node kernels
    const int gG = (NN + 63) / 64;            // tf32 GEMM blocks (BM=64)

    // CSR build
    k_detect_zero<<<gN, T>>>(ei);
    k_hist<<<gE, T>>>(ei);
    k_scan1<<<SCAN_NB, SCAN_B>>>();
    k_scan2<<<1, 128>>>();
    k_scan3<<<SCAN_NB, SCAN_B>>>();
    k_scatter<<<gE, T>>>(ei);

    // Layer 1
    k_gemm1<<<gG, 128>>>(x, W1);
    k_agg1<<<gW, T>>>(b1);

    // Layer 2
    k_gemm2<<<gG, 128>>>(Wmu, Wlv);
    k_agg2<<<gW, T>>>(bmu, blv, out);
}

// round 7
// speedup vs baseline: 4.9987x; 1.1153x over previous
#include <cuda_runtime.h>

// Problem shape (fixed by the dataset)
#define NN    100000
#define EE    1600000
#define IN_F  256
#define HID_F 64
#define OUT_F 32

#define SCAN_B   1024
#define SCAN_NB  ((NN + SCAN_B - 1) / SCAN_B)   // 98

// ----------------------------------------------------------------------------
// Scratch (__device__ globals; no dynamic allocation allowed)
// ----------------------------------------------------------------------------
__device__ float g_dinv[NN];          // rsqrt(1 + in-degree)
__device__ int   g_cnt[NN];           // in-degree histogram
__device__ int   g_rowptr[NN + 1];    // CSR row pointers (by dst)
__device__ int   g_cur[NN];           // scatter cursors
__device__ int   g_bsum[SCAN_NB];     // block sums for scan
__device__ int2  g_csr[EE];           // {src, __float_as_int(norm)}, CSR order
__device__ float g_t[NN * HID_F];     // x@W1, later h@[Wmu|Wlv]
__device__ float g_agg[NN * HID_F];   // h after layer-1 (bias+relu applied)
__device__ int   g_idx64;             // 1 if edge_index is int64, 0 if int32

__device__ __forceinline__ int edge_at(const void* ei, long long i) {
    if (g_idx64) return (int)((const long long*)ei)[i];
    return ((const int*)ei)[i];
}

// ----------------------------------------------------------------------------
// Fused: zero histogram + parallel dtype detection (warp ballot)
// ----------------------------------------------------------------------------
__global__ void k_detect_zero(const void* ei) {
    int i = blockIdx.x * blockDim.x + threadIdx.x;
    if (i < NN) g_cnt[i] = 0;
    if (blockIdx.x == 0 && threadIdx.x < 32) {
        const long long* p = (const long long*)ei;
        bool ok = true;
#pragma unroll
        for (int j = 0; j < 2; j++) {
            long long v = p[threadIdx.x + j * 32];
            if (v < 0 || v >= NN) ok = false;
        }
        unsigned m = __ballot_sync(0xffffffffu, ok);
        if (threadIdx.x == 0) g_idx64 = (m == 0xffffffffu) ? 1 : 0;
    }
}

__global__ void k_hist(const void* ei) {
    int e = blockIdx.x * blockDim.x + threadIdx.x;
    if (e < EE) atomicAdd(&g_cnt[edge_at(ei, (long long)EE + e)], 1);
}

// ----------------------------------------------------------------------------
// Exclusive scan of g_cnt -> g_rowptr, dinv fused in stage 1
// ----------------------------------------------------------------------------
__global__ void k_scan1() {
    __shared__ int sh[SCAN_B];
    int tid = threadIdx.x;
    int i = blockIdx.x * SCAN_B + tid;
    int v = (i < NN) ? g_cnt[i] : 0;
    if (i < NN) g_dinv[i] = rsqrtf((float)(1 + v));   // +1 self-loop
    sh[tid] = v;
    __syncthreads();
    for (int off = 1; off < SCAN_B; off <<= 1) {
        int t = 0;
        if (tid >= off) t = sh[tid - off];
        __syncthreads();
        if (tid >= off) sh[tid] += t;
        __syncthreads();
    }
    if (i < NN) g_rowptr[i] = sh[tid] - v;            // exclusive
    if (tid == SCAN_B - 1) g_bsum[blockIdx.x] = sh[tid];
}

// stage 2: parallel scan of 98 block sums in a single 128-thread block
__global__ void k_scan2() {
    __shared__ int wsum[4];
    int t = threadIdx.x;                 // 0..127
    int lane = t & 31, warp = t >> 5;
    int v = (t < SCAN_NB) ? g_bsum[t] : 0;
    int incl = v;
#pragma unroll
    for (int off = 1; off < 32; off <<= 1) {
        int u = __shfl_up_sync(0xffffffffu, incl, off);
        if (lane >= off) incl += u;
    }
    if (lane == 31) wsum[warp] = incl;
    __syncthreads();
    if (warp == 0 && lane < 4) {
        int w = wsum[lane];
#pragma unroll
        for (int off = 1; off < 4; off <<= 1) {
            int u = __shfl_up_sync(0x0000000fu, w, off);
            if (lane >= off) w += u;
        }
        wsum[lane] = w;
    }
    __syncthreads();
    int base = (warp > 0) ? wsum[warp - 1] : 0;
    if (t < SCAN_NB) g_bsum[t] = base + incl - v;    // exclusive
    if (t == 0) g_rowptr[NN] = EE;
}

// stage 3: add block offsets, init cursors
__global__ void k_scan3() {
    int i = blockIdx.x * SCAN_B + threadIdx.x;
    if (i < NN) {
        int r = g_rowptr[i] + g_bsum[blockIdx.x];
        g_rowptr[i] = r;
        g_cur[i] = r;
    }
}

__global__ void k_scatter(const void* ei) {
    int e = blockIdx.x * blockDim.x + threadIdx.x;
    if (e < EE) {
        int s = edge_at(ei, e);
        int d = edge_at(ei, (long long)EE + e);
        int pos = atomicAdd(&g_cur[d], 1);
        float nv = g_dinv[s] * g_dinv[d];
        g_csr[pos] = make_int2(s, __float_as_int(nv));
    }
}

// ----------------------------------------------------------------------------
// tf32 tensor-core GEMM helpers
// ----------------------------------------------------------------------------
__device__ __forceinline__ unsigned f2tf32(float f) {
    unsigned r;
    asm("cvt.rna.tf32.f32 %0, %1;" : "=r"(r) : "f"(f));
    return r;
}

__device__ __forceinline__ void mma_tf32(float* d, const unsigned* a, const unsigned* b) {
    asm volatile(
        "mma.sync.aligned.m16n8k8.row.col.f32.tf32.tf32.f32 "
        "{%0,%1,%2,%3}, {%4,%5,%6,%7}, {%8,%9}, {%0,%1,%2,%3};\n"
        : "+f"(d[0]), "+f"(d[1]), "+f"(d[2]), "+f"(d[3])
        : "r"(a[0]), "r"(a[1]), "r"(a[2]), "r"(a[3]), "r"(b[0]), "r"(b[1]));
}

__device__ __forceinline__ float4 cvt4(float4 v) {
    return make_float4(__uint_as_float(f2tf32(v.x)), __uint_as_float(f2tf32(v.y)),
                       __uint_as_float(f2tf32(v.z)), __uint_as_float(f2tf32(v.w)));
}

// ----------------------------------------------------------------------------
// GEMM1: g_t = x @ W1   [NN,256]x[256,64], tf32 mma, BM=64 per block (4 warps),
// software-pipelined: prefetch next k-chunk into registers during mma
// ----------------------------------------------------------------------------
__global__ void k_gemm1(const float* __restrict__ x, const float* __restrict__ W1) {
    __shared__ float sx[64][36];   // x tile (tf32 bits), row-major [m][k]
    __shared__ float sw[64][36];   // W chunk transposed [n][k]
    int tid = threadIdx.x;
    int warp = tid >> 5, lane = tid & 31;
    int g = lane >> 2, tg = lane & 3;
    long long bm0 = (long long)blockIdx.x * 64;

    // per-thread load coordinates
    int xr_ = tid >> 3, xc4 = tid & 7;        // +j*16 rows
    int wkr = tid >> 4, wc4 = tid & 15;       // +j*8  k-rows

    float acc[8][4];
#pragma unroll
    for (int nt = 0; nt < 8; nt++)
#pragma unroll
        for (int q = 0; q < 4; q++) acc[nt][q] = 0.0f;

    float4 px[4], pw[4];
    // prefetch chunk 0
#pragma unroll
    for (int j = 0; j < 4; j++) {
        long long row = bm0 + xr_ + j * 16;
        px[j] = (row < NN) ? *(const float4*)(x + row * IN_F + xc4 * 4)
                           : make_float4(0.f, 0.f, 0.f, 0.f);
        pw[j] = *(const float4*)(W1 + (long long)(wkr + j * 8) * 64 + wc4 * 4);
    }

    for (int k0 = 0; k0 < IN_F; k0 += 32) {
        // store prefetched chunk to smem (with tf32 cvt)
#pragma unroll
        for (int j = 0; j < 4; j++) {
            *(float4*)&sx[xr_ + j * 16][xc4 * 4] = cvt4(px[j]);
            float4 c = cvt4(pw[j]);
            sw[wc4 * 4 + 0][wkr + j * 8] = c.x;
            sw[wc4 * 4 + 1][wkr + j * 8] = c.y;
            sw[wc4 * 4 + 2][wkr + j * 8] = c.z;
            sw[wc4 * 4 + 3][wkr + j * 8] = c.w;
        }
        __syncthreads();

        // issue prefetch for next chunk (overlaps with mma below)
        int kn = k0 + 32;
        if (kn < IN_F) {
#pragma unroll
            for (int j = 0; j < 4; j++) {
                long long row = bm0 + xr_ + j * 16;
                px[j] = (row < NN) ? *(const float4*)(x + row * IN_F + kn + xc4 * 4)
                                   : make_float4(0.f, 0.f, 0.f, 0.f);
                pw[j] = *(const float4*)(W1 + (long long)(kn + wkr + j * 8) * 64 + wc4 * 4);
            }
        }

#pragma unroll
        for (int kk = 0; kk < 32; kk += 8) {
            unsigned a[4];
            a[0] = __float_as_uint(sx[warp * 16 + g][kk + tg]);
            a[1] = __float_as_uint(sx[warp * 16 + g + 8][kk + tg]);
            a[2] = __float_as_uint(sx[warp * 16 + g][kk + tg + 4]);
            a[3] = __float_as_uint(sx[warp * 16 + g + 8][kk + tg + 4]);
#pragma unroll
            for (int nt = 0; nt < 8; nt++) {
                unsigned b[2];
                b[0] = __float_as_uint(sw[nt * 8 + g][kk + tg]);
                b[1] = __float_as_uint(sw[nt * 8 + g][kk + tg + 4]);
                mma_tf32(acc[nt], a, b);
            }
        }
        __syncthreads();
    }
    long long r0 = bm0 + warp * 16 + g;
#pragma unroll
    for (int nt = 0; nt < 8; nt++) {
        int col = nt * 8 + tg * 2;
        if (r0 < NN)     *(float2*)&g_t[r0 * 64 + col]       = make_float2(acc[nt][0], acc[nt][1]);
        if (r0 + 8 < NN) *(float2*)&g_t[(r0 + 8) * 64 + col] = make_float2(acc[nt][2], acc[nt][3]);
    }
}

// ----------------------------------------------------------------------------
// GEMM2: g_t = h @ [Wmu|Wlv]   [NN,64]x[64,64], tf32 mma (h in g_agg)
// ----------------------------------------------------------------------------
__global__ void k_gemm2(const float* __restrict__ Wmu, const float* __restrict__ Wlv) {
    __shared__ float sx[64][36];
    __shared__ float sw[64][36];   // [n][k]
    int tid = threadIdx.x;
    int warp = tid >> 5, lane = tid & 31;
    int g = lane >> 2, tg = lane & 3;
    long long bm0 = (long long)blockIdx.x * 64;

    float acc[8][4];
#pragma unroll
    for (int nt = 0; nt < 8; nt++)
#pragma unroll
        for (int q = 0; q < 4; q++) acc[nt][q] = 0.0f;

    for (int k0 = 0; k0 < HID_F; k0 += 32) {
        __syncthreads();
#pragma unroll
        for (int j = 0; j < 4; j++) {
            int idx = tid + j * 128;
            int r = idx >> 3, c4 = idx & 7;
            long long row = bm0 + r;
            float4 v = make_float4(0.f, 0.f, 0.f, 0.f);
            if (row < NN) v = *(const float4*)(g_agg + row * HID_F + k0 + c4 * 4);
            *(float4*)&sx[r][c4 * 4] = cvt4(v);
        }
        // combined weight chunk: cols 0..31 = Wmu[:,0..31], cols 32..63 = Wlv
#pragma unroll
        for (int j = 0; j < 4; j++) {
            int idx = tid + j * 128;
            int kr = idx >> 4, c4 = idx & 15;
            const float* Wsrc = (c4 < 8) ? Wmu : Wlv;
            int cc4 = (c4 < 8) ? c4 : (c4 - 8);
            float4 v = *(const float4*)(Wsrc + (long long)(k0 + kr) * 32 + cc4 * 4);
            float4 c = cvt4(v);
            sw[c4 * 4 + 0][kr] = c.x;
            sw[c4 * 4 + 1][kr] = c.y;
            sw[c4 * 4 + 2][kr] = c.z;
            sw[c4 * 4 + 3][kr] = c.w;
        }
        __syncthreads();
#pragma unroll
        for (int kk = 0; kk < 32; kk += 8) {
            unsigned a[4];
            a[0] = __float_as_uint(sx[warp * 16 + g][kk + tg]);
            a[1] = __float_as_uint(sx[warp * 16 + g + 8][kk + tg]);
            a[2] = __float_as_uint(sx[warp * 16 + g][kk + tg + 4]);
            a[3] = __float_as_uint(sx[warp * 16 + g + 8][kk + tg + 4]);
#pragma unroll
            for (int nt = 0; nt < 8; nt++) {
                unsigned b[2];
                b[0] = __float_as_uint(sw[nt * 8 + g][kk + tg]);
                b[1] = __float_as_uint(sw[nt * 8 + g][kk + tg + 4]);
                mma_tf32(acc[nt], a, b);
            }
        }
    }
    long long r0 = bm0 + warp * 16 + g;
#pragma unroll
    for (int nt = 0; nt < 8; nt++) {
        int col = nt * 8 + tg * 2;
        if (r0 < NN)     *(float2*)&g_t[r0 * 64 + col]       = make_float2(acc[nt][0], acc[nt][1]);
        if (r0 + 8 < NN) *(float2*)&g_t[(r0 + 8) * 64 + col] = make_float2(acc[nt][2], acc[nt][3]);
    }
}

// ----------------------------------------------------------------------------
// CSR segment-sum aggregation: one warp per node; two half-warps each process
// a different edge per step (float4 per 16 lanes covers all 64 features).
// ----------------------------------------------------------------------------
__global__ void k_agg1(const float* __restrict__ b1) {
    int w = (blockIdx.x * blockDim.x + threadIdx.x) >> 5;
    int lane = threadIdx.x & 31;
    if (w >= NN) return;
    int h = lane >> 4, l16 = lane & 15;

    const float4* t4 = (const float4*)g_t;
    float dv = g_dinv[w];
    float4 self = t4[(long long)w * 16 + l16];
    float ws = (h == 0) ? dv * dv : 0.0f;
    float4 acc = make_float4(self.x * ws, self.y * ws, self.z * ws, self.w * ws);

    int beg = g_rowptr[w], end = g_rowptr[w + 1];
    for (int base = beg; base < end; base += 32) {
        int n = min(32, end - base);
        int2 e = make_int2(0, 0);
        if (lane < n) e = g_csr[base + lane];
        int steps = (n + 1) >> 1;
        for (int j = 0; j < steps; j++) {
            int idx = 2 * j + h;
            int   sj = __shfl_sync(0xffffffffu, e.x, idx);
            float nj = __int_as_float(__shfl_sync(0xffffffffu, e.y, idx));
            if (idx < n) {
                float4 v = t4[(long long)sj * 16 + l16];
                acc.x += v.x * nj;
                acc.y += v.y * nj;
                acc.z += v.z * nj;
                acc.w += v.w * nj;
            }
        }
    }
    acc.x += __shfl_xor_sync(0xffffffffu, acc.x, 16);
    acc.y += __shfl_xor_sync(0xffffffffu, acc.y, 16);
    acc.z += __shfl_xor_sync(0xffffffffu, acc.z, 16);
    acc.w += __shfl_xor_sync(0xffffffffu, acc.w, 16);
    if (h == 0) {
        float4 b = ((const float4*)b1)[l16];
        float4 r = make_float4(fmaxf(acc.x + b.x, 0.0f), fmaxf(acc.y + b.y, 0.0f),
                               fmaxf(acc.z + b.z, 0.0f), fmaxf(acc.w + b.w, 0.0f));
        ((float4*)g_agg)[(long long)w * 16 + l16] = r;
    }
}

__global__ void k_agg2(const float* __restrict__ bmu, const float* __restrict__ blv,
                       float* __restrict__ out) {
    int w = (blockIdx.x * blockDim.x + threadIdx.x) >> 5;
    int lane = threadIdx.x & 31;
    if (w >= NN) return;
    int h = lane >> 4, l16 = lane & 15;

    const float4* t4 = (const float4*)g_t;
    float dv = g_dinv[w];
    float4 self = t4[(long long)w * 16 + l16];
    float ws = (h == 0) ? dv * dv : 0.0f;
    float4 acc = make_float4(self.x * ws, self.y * ws, self.z * ws, self.w * ws);

    int beg = g_rowptr[w], end = g_rowptr[w + 1];
    for (int base = beg; base < end; base += 32) {
        int n = min(32, end - base);
        int2 e = make_int2(0, 0);
        if (lane < n) e = g_csr[base + lane];
        int steps = (n + 1) >> 1;
        for (int j = 0; j < steps; j++) {
            int idx = 2 * j + h;
            int   sj = __shfl_sync(0xffffffffu, e.x, idx);
            float nj = __int_as_float(__shfl_sync(0xffffffffu, e.y, idx));
            if (idx < n) {
                float4 v = t4[(long long)sj * 16 + l16];
                acc.x += v.x * nj;
                acc.y += v.y * nj;
                acc.z += v.z * nj;
                acc.w += v.w * nj;
            }
        }
    }
    acc.x += __shfl_xor_sync(0xffffffffu, acc.x, 16);
    acc.y += __shfl_xor_sync(0xffffffffu, acc.y, 16);
    acc.z += __shfl_xor_sync(0xffffffffu, acc.z, 16);
    acc.w += __shfl_xor_sync(0xffffffffu, acc.w, 16);
    if (h == 0) {
        float4* o4 = (float4*)out;
        if (l16 < 8) {      // features 0..31 -> mu
            float4 b = ((const float4*)bmu)[l16];
            o4[(long long)w * 8 + l16] =
                make_float4(acc.x + b.x, acc.y + b.y, acc.z + b.z, acc.w + b.w);
        } else {            // features 32..63 -> logvar
            float4 b = ((const float4*)blv)[l16 - 8];
            o4[(long long)NN * 8 + (long long)w * 8 + (l16 - 8)] =
                make_float4(acc.x + b.x, acc.y + b.y, acc.z + b.z, acc.w + b.w);
        }
    }
}

// ----------------------------------------------------------------------------
// Launch
// ----------------------------------------------------------------------------
extern "C" void kernel_launch(void* const* d_in, const int* in_sizes, int n_in,
                              void* d_out, int out_size) {
    const float* x   = (const float*)d_in[0];
    const void*  ei  = d_in[1];
    const float* W1  = (const float*)d_in[2];
    const float* b1  = (const float*)d_in[3];
    const float* Wmu = (const float*)d_in[4];
    const float* bmu = (const float*)d_in[5];
    const float* Wlv = (const float*)d_in[6];
    const float* blv = (const float*)d_in[7];
    float* out = (float*)d_out;

    const int T = 256;
    const int gN = (NN + T - 1) / T;
    const int gE = (EE + T - 1) / T;
    const int gW = (NN * 32 + T - 1) / T;     // warp-per-node kernels
    const int gG = (NN + 63) / 64;            // tf32 GEMM blocks (BM=64)

    // CSR build
    k_detect_zero<<<gN, T>>>(ei);
    k_hist<<<gE, T>>>(ei);
    k_scan1<<<SCAN_NB, SCAN_B>>>();
    k_scan2<<<1, 128>>>();
    k_scan3<<<SCAN_NB, SCAN_B>>>();
    k_scatter<<<gE, T>>>(ei);

    // Layer 1
    k_gemm1<<<gG, 128>>>(x, W1);
    k_agg1<<<gW, T>>>(b1);

    // Layer 2
    k_gemm2<<<gG, 128>>>(Wmu, Wlv);
    k_agg2<<<gW, T>>>(bmu, blv, out);
}

// round 9
// speedup vs baseline: 5.2485x; 1.0500x over previous
#include <cuda_runtime.h>

// Problem shape (fixed by the dataset)
#define NN    100000
#define EE    1600000
#define IN_F  256
#define HID_F 64
#define OUT_F 32

#define SCAN_B   1024
#define SCAN_NB  ((NN + SCAN_B - 1) / SCAN_B)   // 98

// ----------------------------------------------------------------------------
// Scratch (__device__ globals; no dynamic allocation allowed)
// ----------------------------------------------------------------------------
__device__ float g_dinv[NN];          // rsqrt(1 + in-degree)
__device__ int   g_cnt[NN];           // in-degree histogram
__device__ int   g_rowptr[NN + 1];    // CSR row pointers (by dst)
__device__ int   g_cur[NN];           // scatter cursors
__device__ int   g_bsum[SCAN_NB];     // block sums for scan
__device__ int2  g_csr[EE];           // {src, __float_as_int(norm)}, CSR order
__device__ float g_t[NN * HID_F];     // x@W1, later h@[Wmu|Wlv]
__device__ float g_agg[NN * HID_F];   // h after layer-1 (bias+relu applied)
__device__ int   g_idx64;             // 1 if edge_index is int64, 0 if int32

__device__ __forceinline__ int edge_at(const void* ei, long long i) {
    if (g_idx64) return (int)((const long long*)ei)[i];
    return ((const int*)ei)[i];
}

// ----------------------------------------------------------------------------
// Fused: zero histogram + parallel dtype detection (warp ballot)
// ----------------------------------------------------------------------------
__global__ void k_detect_zero(const void* ei) {
    int i = blockIdx.x * blockDim.x + threadIdx.x;
    if (i < NN) g_cnt[i] = 0;
    if (blockIdx.x == 0 && threadIdx.x < 32) {
        const long long* p = (const long long*)ei;
        bool ok = true;
#pragma unroll
        for (int j = 0; j < 2; j++) {
            long long v = p[threadIdx.x + j * 32];
            if (v < 0 || v >= NN) ok = false;
        }
        unsigned m = __ballot_sync(0xffffffffu, ok);
        if (threadIdx.x == 0) g_idx64 = (m == 0xffffffffu) ? 1 : 0;
    }
}

__global__ void k_hist(const void* ei) {
    int e = blockIdx.x * blockDim.x + threadIdx.x;
    if (e < EE) atomicAdd(&g_cnt[edge_at(ei, (long long)EE + e)], 1);
}

// ----------------------------------------------------------------------------
// Exclusive scan of g_cnt -> g_rowptr, dinv fused in stage 1
// ----------------------------------------------------------------------------
__global__ void k_scan1() {
    __shared__ int sh[SCAN_B];
    int tid = threadIdx.x;
    int i = blockIdx.x * SCAN_B + tid;
    int v = (i < NN) ? g_cnt[i] : 0;
    if (i < NN) g_dinv[i] = rsqrtf((float)(1 + v));   // +1 self-loop
    sh[tid] = v;
    __syncthreads();
    for (int off = 1; off < SCAN_B; off <<= 1) {
        int t = 0;
        if (tid >= off) t = sh[tid - off];
        __syncthreads();
        if (tid >= off) sh[tid] += t;
        __syncthreads();
    }
    if (i < NN) g_rowptr[i] = sh[tid] - v;            // exclusive
    if (tid == SCAN_B - 1) g_bsum[blockIdx.x] = sh[tid];
}

// stage 2 (fused): each block computes its own prefix over the 98 block sums
// with a strided warp reduction, then adds it and initializes cursors.
__global__ void k_scan3() {
    __shared__ int s_off;
    int tid = threadIdx.x;
    if (tid < 32) {
        int bid = blockIdx.x;
        int part = 0;
        for (int k = tid; k < bid; k += 32) part += g_bsum[k];
#pragma unroll
        for (int off = 16; off > 0; off >>= 1)
            part += __shfl_down_sync(0xffffffffu, part, off);
        if (tid == 0) s_off = part;
    }
    __syncthreads();
    int i = blockIdx.x * SCAN_B + tid;
    if (i < NN) {
        int r = g_rowptr[i] + s_off;
        g_rowptr[i] = r;
        g_cur[i] = r;
    }
    if (blockIdx.x == 0 && tid == 0) g_rowptr[NN] = EE;
}

__global__ void k_scatter(const void* ei) {
    int e = blockIdx.x * blockDim.x + threadIdx.x;
    if (e < EE) {
        int s = edge_at(ei, e);
        int d = edge_at(ei, (long long)EE + e);
        int pos = atomicAdd(&g_cur[d], 1);
        float nv = g_dinv[s] * g_dinv[d];
        g_csr[pos] = make_int2(s, __float_as_int(nv));
    }
}

// ----------------------------------------------------------------------------
// tf32 tensor-core GEMM helpers
// ----------------------------------------------------------------------------
__device__ __forceinline__ unsigned f2tf32(float f) {
    unsigned r;
    asm("cvt.rna.tf32.f32 %0, %1;" : "=r"(r) : "f"(f));
    return r;
}

__device__ __forceinline__ void mma_tf32(float* d, const unsigned* a, const unsigned* b) {
    asm volatile(
        "mma.sync.aligned.m16n8k8.row.col.f32.tf32.tf32.f32 "
        "{%0,%1,%2,%3}, {%4,%5,%6,%7}, {%8,%9}, {%0,%1,%2,%3};\n"
        : "+f"(d[0]), "+f"(d[1]), "+f"(d[2]), "+f"(d[3])
        : "r"(a[0]), "r"(a[1]), "r"(a[2]), "r"(a[3]), "r"(b[0]), "r"(b[1]));
}

__device__ __forceinline__ float4 cvt4(float4 v) {
    return make_float4(__uint_as_float(f2tf32(v.x)), __uint_as_float(f2tf32(v.y)),
                       __uint_as_float(f2tf32(v.z)), __uint_as_float(f2tf32(v.w)));
}

// ----------------------------------------------------------------------------
// GEMM1: g_t = x @ W1   [NN,256]x[256,64], tf32 mma, BM=64 per block (4 warps),
// software-pipelined: prefetch next k-chunk into registers during mma
// ----------------------------------------------------------------------------
__global__ void k_gemm1(const float* __restrict__ x, const float* __restrict__ W1) {
    __shared__ float sx[64][36];   // x tile (tf32 bits), row-major [m][k]
    __shared__ float sw[64][36];   // W chunk transposed [n][k]
    int tid = threadIdx.x;
    int warp = tid >> 5, lane = tid & 31;
    int g = lane >> 2, tg = lane & 3;
    long long bm0 = (long long)blockIdx.x * 64;

    // per-thread load coordinates
    int xr_ = tid >> 3, xc4 = tid & 7;        // +j*16 rows
    int wkr = tid >> 4, wc4 = tid & 15;       // +j*8  k-rows

    float acc[8][4];
#pragma unroll
    for (int nt = 0; nt < 8; nt++)
#pragma unroll
        for (int q = 0; q < 4; q++) acc[nt][q] = 0.0f;

    float4 px[4], pw[4];
    // prefetch chunk 0
#pragma unroll
    for (int j = 0; j < 4; j++) {
        long long row = bm0 + xr_ + j * 16;
        px[j] = (row < NN) ? *(const float4*)(x + row * IN_F + xc4 * 4)
                           : make_float4(0.f, 0.f, 0.f, 0.f);
        pw[j] = *(const float4*)(W1 + (long long)(wkr + j * 8) * 64 + wc4 * 4);
    }

    for (int k0 = 0; k0 < IN_F; k0 += 32) {
        // store prefetched chunk to smem (with tf32 cvt)
#pragma unroll
        for (int j = 0; j < 4; j++) {
            *(float4*)&sx[xr_ + j * 16][xc4 * 4] = cvt4(px[j]);
            float4 c = cvt4(pw[j]);
            sw[wc4 * 4 + 0][wkr + j * 8] = c.x;
            sw[wc4 * 4 + 1][wkr + j * 8] = c.y;
            sw[wc4 * 4 + 2][wkr + j * 8] = c.z;
            sw[wc4 * 4 + 3][wkr + j * 8] = c.w;
        }
        __syncthreads();

        // issue prefetch for next chunk (overlaps with mma below)
        int kn = k0 + 32;
        if (kn < IN_F) {
#pragma unroll
            for (int j = 0; j < 4; j++) {
                long long row = bm0 + xr_ + j * 16;
                px[j] = (row < NN) ? *(const float4*)(x + row * IN_F + kn + xc4 * 4)
                                   : make_float4(0.f, 0.f, 0.f, 0.f);
                pw[j] = *(const float4*)(W1 + (long long)(kn + wkr + j * 8) * 64 + wc4 * 4);
            }
        }

#pragma unroll
        for (int kk = 0; kk < 32; kk += 8) {
            unsigned a[4];
            a[0] = __float_as_uint(sx[warp * 16 + g][kk + tg]);
            a[1] = __float_as_uint(sx[warp * 16 + g + 8][kk + tg]);
            a[2] = __float_as_uint(sx[warp * 16 + g][kk + tg + 4]);
            a[3] = __float_as_uint(sx[warp * 16 + g + 8][kk + tg + 4]);
#pragma unroll
            for (int nt = 0; nt < 8; nt++) {
                unsigned b[2];
                b[0] = __float_as_uint(sw[nt * 8 + g][kk + tg]);
                b[1] = __float_as_uint(sw[nt * 8 + g][kk + tg + 4]);
                mma_tf32(acc[nt], a, b);
            }
        }
        __syncthreads();
    }
    long long r0 = bm0 + warp * 16 + g;
#pragma unroll
    for (int nt = 0; nt < 8; nt++) {
        int col = nt * 8 + tg * 2;
        if (r0 < NN)     *(float2*)&g_t[r0 * 64 + col]       = make_float2(acc[nt][0], acc[nt][1]);
        if (r0 + 8 < NN) *(float2*)&g_t[(r0 + 8) * 64 + col] = make_float2(acc[nt][2], acc[nt][3]);
    }
}

// ----------------------------------------------------------------------------
// GEMM2: g_t = h @ [Wmu|Wlv]   [NN,64]x[64,64], tf32 mma (h in g_agg)
// ----------------------------------------------------------------------------
__global__ void k_gemm2(const float* __restrict__ Wmu, const float* __restrict__ Wlv) {
    __shared__ float sx[64][36];
    __shared__ float sw[64][36];   // [n][k]
    int tid = threadIdx.x;
    int warp = tid >> 5, lane = tid & 31;
    int g = lane >> 2, tg = lane & 3;
    long long bm0 = (long long)blockIdx.x * 64;

    float acc[8][4];
#pragma unroll
    for (int nt = 0; nt < 8; nt++)
#pragma unroll
        for (int q = 0; q < 4; q++) acc[nt][q] = 0.0f;

    for (int k0 = 0; k0 < HID_F; k0 += 32) {
        __syncthreads();
#pragma unroll
        for (int j = 0; j < 4; j++) {
            int idx = tid + j * 128;
            int r = idx >> 3, c4 = idx & 7;
            long long row = bm0 + r;
            float4 v = make_float4(0.f, 0.f, 0.f, 0.f);
            if (row < NN) v = *(const float4*)(g_agg + row * HID_F + k0 + c4 * 4);
            *(float4*)&sx[r][c4 * 4] = cvt4(v);
        }
        // combined weight chunk: cols 0..31 = Wmu[:,0..31], cols 32..63 = Wlv
#pragma unroll
        for (int j = 0; j < 4; j++) {
            int idx = tid + j * 128;
            int kr = idx >> 4, c4 = idx & 15;
            const float* Wsrc = (c4 < 8) ? Wmu : Wlv;
            int cc4 = (c4 < 8) ? c4 : (c4 - 8);
            float4 v = *(const float4*)(Wsrc + (long long)(k0 + kr) * 32 + cc4 * 4);
            float4 c = cvt4(v);
            sw[c4 * 4 + 0][kr] = c.x;
            sw[c4 * 4 + 1][kr] = c.y;
            sw[c4 * 4 + 2][kr] = c.z;
            sw[c4 * 4 + 3][kr] = c.w;
        }
        __syncthreads();
#pragma unroll
        for (int kk = 0; kk < 32; kk += 8) {
            unsigned a[4];
            a[0] = __float_as_uint(sx[warp * 16 + g][kk + tg]);
            a[1] = __float_as_uint(sx[warp * 16 + g + 8][kk + tg]);
            a[2] = __float_as_uint(sx[warp * 16 + g][kk + tg + 4]);
            a[3] = __float_as_uint(sx[warp * 16 + g + 8][kk + tg + 4]);
#pragma unroll
            for (int nt = 0; nt < 8; nt++) {
                unsigned b[2];
                b[0] = __float_as_uint(sw[nt * 8 + g][kk + tg]);
                b[1] = __float_as_uint(sw[nt * 8 + g][kk + tg + 4]);
                mma_tf32(acc[nt], a, b);
            }
        }
    }
    long long r0 = bm0 + warp * 16 + g;
#pragma unroll
    for (int nt = 0; nt < 8; nt++) {
        int col = nt * 8 + tg * 2;
        if (r0 < NN)     *(float2*)&g_t[r0 * 64 + col]       = make_float2(acc[nt][0], acc[nt][1]);
        if (r0 + 8 < NN) *(float2*)&g_t[(r0 + 8) * 64 + col] = make_float2(acc[nt][2], acc[nt][3]);
    }
}

// ----------------------------------------------------------------------------
// CSR segment-sum aggregation: one warp per node; two half-warps each process
// a different edge per step (float4 per 16 lanes covers all 64 features).
// ----------------------------------------------------------------------------
__global__ void k_agg1(const float* __restrict__ b1) {
    int w = (blockIdx.x * blockDim.x + threadIdx.x) >> 5;
    int lane = threadIdx.x & 31;
    if (w >= NN) return;
    int h = lane >> 4, l16 = lane & 15;

    const float4* t4 = (const float4*)g_t;
    float dv = g_dinv[w];
    float4 self = t4[(long long)w * 16 + l16];
    float ws = (h == 0) ? dv * dv : 0.0f;
    float4 acc = make_float4(self.x * ws, self.y * ws, self.z * ws, self.w * ws);

    int beg = g_rowptr[w], end = g_rowptr[w + 1];
    for (int base = beg; base < end; base += 32) {
        int n = min(32, end - base);
        int2 e = make_int2(0, 0);
        if (lane < n) e = g_csr[base + lane];
        int steps = (n + 1) >> 1;
        for (int j = 0; j < steps; j++) {
            int idx = 2 * j + h;
            int   sj = __shfl_sync(0xffffffffu, e.x, idx);
            float nj = __int_as_float(__shfl_sync(0xffffffffu, e.y, idx));
            if (idx < n) {
                float4 v = t4[(long long)sj * 16 + l16];
                acc.x += v.x * nj;
                acc.y += v.y * nj;
                acc.z += v.z * nj;
                acc.w += v.w * nj;
            }
        }
    }
    acc.x += __shfl_xor_sync(0xffffffffu, acc.x, 16);
    acc.y += __shfl_xor_sync(0xffffffffu, acc.y, 16);
    acc.z += __shfl_xor_sync(0xffffffffu, acc.z, 16);
    acc.w += __shfl_xor_sync(0xffffffffu, acc.w, 16);
    if (h == 0) {
        float4 b = ((const float4*)b1)[l16];
        float4 r = make_float4(fmaxf(acc.x + b.x, 0.0f), fmaxf(acc.y + b.y, 0.0f),
                               fmaxf(acc.z + b.z, 0.0f), fmaxf(acc.w + b.w, 0.0f));
        ((float4*)g_agg)[(long long)w * 16 + l16] = r;
    }
}

__global__ void k_agg2(const float* __restrict__ bmu, const float* __restrict__ blv,
                       float* __restrict__ out) {
    int w = (blockIdx.x * blockDim.x + threadIdx.x) >> 5;
    int lane = threadIdx.x & 31;
    if (w >= NN) return;
    int h = lane >> 4, l16 = lane & 15;

    const float4* t4 = (const float4*)g_t;
    float dv = g_dinv[w];
    float4 self = t4[(long long)w * 16 + l16];
    float ws = (h == 0) ? dv * dv : 0.0f;
    float4 acc = make_float4(self.x * ws, self.y * ws, self.z * ws, self.w * ws);

    int beg = g_rowptr[w], end = g_rowptr[w + 1];
    for (int base = beg; base < end; base += 32) {
        int n = min(32, end - base);
        int2 e = make_int2(0, 0);
        if (lane < n) e = g_csr[base + lane];
        int steps = (n + 1) >> 1;
        for (int j = 0; j < steps; j++) {
            int idx = 2 * j + h;
            int   sj = __shfl_sync(0xffffffffu, e.x, idx);
            float nj = __int_as_float(__shfl_sync(0xffffffffu, e.y, idx));
            if (idx < n) {
                float4 v = t4[(long long)sj * 16 + l16];
                acc.x += v.x * nj;
                acc.y += v.y * nj;
                acc.z += v.z * nj;
                acc.w += v.w * nj;
            }
        }
    }
    acc.x += __shfl_xor_sync(0xffffffffu, acc.x, 16);
    acc.y += __shfl_xor_sync(0xffffffffu, acc.y, 16);
    acc.z += __shfl_xor_sync(0xffffffffu, acc.z, 16);
    acc.w += __shfl_xor_sync(0xffffffffu, acc.w, 16);
    if (h == 0) {
        float4* o4 = (float4*)out;
        if (l16 < 8) {      // features 0..31 -> mu
            float4 b = ((const float4*)bmu)[l16];
            o4[(long long)w * 8 + l16] =
                make_float4(acc.x + b.x, acc.y + b.y, acc.z + b.z, acc.w + b.w);
        } else {            // features 32..63 -> logvar
            float4 b = ((const float4*)blv)[l16 - 8];
            o4[(long long)NN * 8 + (long long)w * 8 + (l16 - 8)] =
                make_float4(acc.x + b.x, acc.y + b.y, acc.z + b.z, acc.w + b.w);
        }
    }
}

// ----------------------------------------------------------------------------
// Launch: CSR chain forked onto a side stream, overlapping GEMM1.
// Stream/events created once on the first (non-captured) call; during graph
// capture the event record/wait become graph edges. Identical work every call.
// ----------------------------------------------------------------------------
static cudaStream_t g_s2 = 0;
static cudaEvent_t  g_ev_fork = 0, g_ev_join = 0;

extern "C" void kernel_launch(void* const* d_in, const int* in_sizes, int n_in,
                              void* d_out, int out_size) {
    const float* x   = (const float*)d_in[0];
    const void*  ei  = d_in[1];
    const float* W1  = (const float*)d_in[2];
    const float* b1  = (const float*)d_in[3];
    const float* Wmu = (const float*)d_in[4];
    const float* bmu = (const float*)d_in[5];
    const float* Wlv = (const float*)d_in[6];
    const float* blv = (const float*)d_in[7];
    float* out = (float*)d_out;

    if (g_s2 == 0) {
        cudaStreamCreateWithFlags(&g_s2, cudaStreamNonBlocking);
        cudaEventCreateWithFlags(&g_ev_fork, cudaEventDisableTiming);
        cudaEventCreateWithFlags(&g_ev_join, cudaEventDisableTiming);
    }

    const int T = 256;
    const int gN = (NN + T - 1) / T;
    const int gE = (EE + T - 1) / T;
    const int gW = (NN * 32 + T - 1) / T;     // warp-per-node kernels
    const int gG = (NN + 63) / 64;            // tf32 GEMM blocks (BM=64)

    // Fork: CSR build chain on side stream
    cudaEventRecord(g_ev_fork, 0);
    cudaStreamWaitEvent(g_s2, g_ev_fork, 0);
    k_detect_zero<<<gN, T, 0, g_s2>>>(ei);
    k_hist<<<gE, T, 0, g_s2>>>(ei);
    k_scan1<<<SCAN_NB, SCAN_B, 0, g_s2>>>();
    k_scan3<<<SCAN_NB, SCAN_B, 0, g_s2>>>();
    k_scatter<<<gE, T, 0, g_s2>>>(ei);
    cudaEventRecord(g_ev_join, g_s2);

    // Main stream: GEMM1 overlaps the CSR chain
    k_gemm1<<<gG, 128>>>(x, W1);

    // Join: agg1 needs both GEMM1 output and CSR
    cudaStreamWaitEvent(0, g_ev_join, 0);
    k_agg1<<<gW, T>>>(b1);

    // Layer 2
    k_gemm2<<<gG, 128>>>(Wmu, Wlv);
    k_agg2<<<gW, T>>>(bmu, blv, out);
}

// round 10
// speedup vs baseline: 5.5032x; 1.0485x over previous
#include <cuda_runtime.h>
#include <cuda_fp16.h>

// Problem shape (fixed by the dataset)
#define NN    100000
#define EE    1600000
#define IN_F  256
#define HID_F 64
#define OUT_F 32

#define SCAN_B   1024
#define SCAN_NB  ((NN + SCAN_B - 1) / SCAN_B)   // 98

// ----------------------------------------------------------------------------
// Scratch (__device__ globals; no dynamic allocation allowed)
// ----------------------------------------------------------------------------
__device__ float g_dinv[NN];          // rsqrt(1 + in-degree)
__device__ int   g_cnt[NN];           // in-degree histogram
__device__ int   g_rowptr[NN + 1];    // CSR row pointers (by dst)
__device__ int   g_cur[NN];           // scatter cursors
__device__ int   g_bsum[SCAN_NB];     // block sums for scan
__device__ int2  g_csr[EE];           // {src, __float_as_int(norm)}, CSR order
__device__ half2 g_t16[NN * 32];      // x@W1 (later h@[Wmu|Wlv]) in fp16, 128 B/row
__device__ float g_agg[NN * HID_F];   // h after layer-1 (bias+relu, fp32)
__device__ int   g_idx64;             // 1 if edge_index is int64, 0 if int32

__device__ __forceinline__ int edge_at(const void* ei, long long i) {
    if (g_idx64) return (int)((const long long*)ei)[i];
    return ((const int*)ei)[i];
}

// ----------------------------------------------------------------------------
// Fused: zero histogram + parallel dtype detection (warp ballot)
// ----------------------------------------------------------------------------
__global__ void k_detect_zero(const void* ei) {
    int i = blockIdx.x * blockDim.x + threadIdx.x;
    if (i < NN) g_cnt[i] = 0;
    if (blockIdx.x == 0 && threadIdx.x < 32) {
        const long long* p = (const long long*)ei;
        bool ok = true;
#pragma unroll
        for (int j = 0; j < 2; j++) {
            long long v = p[threadIdx.x + j * 32];
            if (v < 0 || v >= NN) ok = false;
        }
        unsigned m = __ballot_sync(0xffffffffu, ok);
        if (threadIdx.x == 0) g_idx64 = (m == 0xffffffffu) ? 1 : 0;
    }
}

__global__ void k_hist(const void* ei) {
    int e = blockIdx.x * blockDim.x + threadIdx.x;
    if (e < EE) atomicAdd(&g_cnt[edge_at(ei, (long long)EE + e)], 1);
}

// ----------------------------------------------------------------------------
// Exclusive scan of g_cnt -> g_rowptr, dinv fused in stage 1
// ----------------------------------------------------------------------------
__global__ void k_scan1() {
    __shared__ int sh[SCAN_B];
    int tid = threadIdx.x;
    int i = blockIdx.x * SCAN_B + tid;
    int v = (i < NN) ? g_cnt[i] : 0;
    if (i < NN) g_dinv[i] = rsqrtf((float)(1 + v));   // +1 self-loop
    sh[tid] = v;
    __syncthreads();
    for (int off = 1; off < SCAN_B; off <<= 1) {
        int t = 0;
        if (tid >= off) t = sh[tid - off];
        __syncthreads();
        if (tid >= off) sh[tid] += t;
        __syncthreads();
    }
    if (i < NN) g_rowptr[i] = sh[tid] - v;            // exclusive
    if (tid == SCAN_B - 1) g_bsum[blockIdx.x] = sh[tid];
}

// stage 2 (fused): each block computes its own prefix over the 98 block sums
// with a strided warp reduction, then adds it and initializes cursors.
__global__ void k_scan3() {
    __shared__ int s_off;
    int tid = threadIdx.x;
    if (tid < 32) {
        int bid = blockIdx.x;
        int part = 0;
        for (int k = tid; k < bid; k += 32) part += g_bsum[k];
#pragma unroll
        for (int off = 16; off > 0; off >>= 1)
            part += __shfl_down_sync(0xffffffffu, part, off);
        if (tid == 0) s_off = part;
    }
    __syncthreads();
    int i = blockIdx.x * SCAN_B + tid;
    if (i < NN) {
        int r = g_rowptr[i] + s_off;
        g_rowptr[i] = r;
        g_cur[i] = r;
    }
    if (blockIdx.x == 0 && tid == 0) g_rowptr[NN] = EE;
}

__global__ void k_scatter(const void* ei) {
    int e = blockIdx.x * blockDim.x + threadIdx.x;
    if (e < EE) {
        int s = edge_at(ei, e);
        int d = edge_at(ei, (long long)EE + e);
        int pos = atomicAdd(&g_cur[d], 1);
        float nv = g_dinv[s] * g_dinv[d];
        g_csr[pos] = make_int2(s, __float_as_int(nv));
    }
}

// ----------------------------------------------------------------------------
// tf32 tensor-core GEMM helpers
// ----------------------------------------------------------------------------
__device__ __forceinline__ unsigned f2tf32(float f) {
    unsigned r;
    asm("cvt.rna.tf32.f32 %0, %1;" : "=r"(r) : "f"(f));
    return r;
}

__device__ __forceinline__ void mma_tf32(float* d, const unsigned* a, const unsigned* b) {
    asm volatile(
        "mma.sync.aligned.m16n8k8.row.col.f32.tf32.tf32.f32 "
        "{%0,%1,%2,%3}, {%4,%5,%6,%7}, {%8,%9}, {%0,%1,%2,%3};\n"
        : "+f"(d[0]), "+f"(d[1]), "+f"(d[2]), "+f"(d[3])
        : "r"(a[0]), "r"(a[1]), "r"(a[2]), "r"(a[3]), "r"(b[0]), "r"(b[1]));
}

__device__ __forceinline__ float4 cvt4(float4 v) {
    return make_float4(__uint_as_float(f2tf32(v.x)), __uint_as_float(f2tf32(v.y)),
                       __uint_as_float(f2tf32(v.z)), __uint_as_float(f2tf32(v.w)));
}

// ----------------------------------------------------------------------------
// GEMM1: g_t16 = fp16(x @ W1)  [NN,256]x[256,64], tf32 mma, BM=64 per block,
// software-pipelined: prefetch next k-chunk into registers during mma
// ----------------------------------------------------------------------------
__global__ void k_gemm1(const float* __restrict__ x, const float* __restrict__ W1) {
    __shared__ float sx[64][36];   // x tile (tf32 bits), row-major [m][k]
    __shared__ float sw[64][36];   // W chunk transposed [n][k]
    int tid = threadIdx.x;
    int warp = tid >> 5, lane = tid & 31;
    int g = lane >> 2, tg = lane & 3;
    long long bm0 = (long long)blockIdx.x * 64;

    int xr_ = tid >> 3, xc4 = tid & 7;        // +j*16 rows
    int wkr = tid >> 4, wc4 = tid & 15;       // +j*8  k-rows

    float acc[8][4];
#pragma unroll
    for (int nt = 0; nt < 8; nt++)
#pragma unroll
        for (int q = 0; q < 4; q++) acc[nt][q] = 0.0f;

    float4 px[4], pw[4];
#pragma unroll
    for (int j = 0; j < 4; j++) {
        long long row = bm0 + xr_ + j * 16;
        px[j] = (row < NN) ? *(const float4*)(x + row * IN_F + xc4 * 4)
                           : make_float4(0.f, 0.f, 0.f, 0.f);
        pw[j] = *(const float4*)(W1 + (long long)(wkr + j * 8) * 64 + wc4 * 4);
    }

    for (int k0 = 0; k0 < IN_F; k0 += 32) {
#pragma unroll
        for (int j = 0; j < 4; j++) {
            *(float4*)&sx[xr_ + j * 16][xc4 * 4] = cvt4(px[j]);
            float4 c = cvt4(pw[j]);
            sw[wc4 * 4 + 0][wkr + j * 8] = c.x;
            sw[wc4 * 4 + 1][wkr + j * 8] = c.y;
            sw[wc4 * 4 + 2][wkr + j * 8] = c.z;
            sw[wc4 * 4 + 3][wkr + j * 8] = c.w;
        }
        __syncthreads();

        int kn = k0 + 32;
        if (kn < IN_F) {
#pragma unroll
            for (int j = 0; j < 4; j++) {
                long long row = bm0 + xr_ + j * 16;
                px[j] = (row < NN) ? *(const float4*)(x + row * IN_F + kn + xc4 * 4)
                                   : make_float4(0.f, 0.f, 0.f, 0.f);
                pw[j] = *(const float4*)(W1 + (long long)(kn + wkr + j * 8) * 64 + wc4 * 4);
            }
        }

#pragma unroll
        for (int kk = 0; kk < 32; kk += 8) {
            unsigned a[4];
            a[0] = __float_as_uint(sx[warp * 16 + g][kk + tg]);
            a[1] = __float_as_uint(sx[warp * 16 + g + 8][kk + tg]);
            a[2] = __float_as_uint(sx[warp * 16 + g][kk + tg + 4]);
            a[3] = __float_as_uint(sx[warp * 16 + g + 8][kk + tg + 4]);
#pragma unroll
            for (int nt = 0; nt < 8; nt++) {
                unsigned b[2];
                b[0] = __float_as_uint(sw[nt * 8 + g][kk + tg]);
                b[1] = __float_as_uint(sw[nt * 8 + g][kk + tg + 4]);
                mma_tf32(acc[nt], a, b);
            }
        }
        __syncthreads();
    }
    long long r0 = bm0 + warp * 16 + g;
#pragma unroll
    for (int nt = 0; nt < 8; nt++) {
        int c2 = nt * 4 + tg;          // half2 column index (covers cols nt*8+tg*2, +1)
        if (r0 < NN)     g_t16[r0 * 32 + c2]       = __floats2half2_rn(acc[nt][0], acc[nt][1]);
        if (r0 + 8 < NN) g_t16[(r0 + 8) * 32 + c2] = __floats2half2_rn(acc[nt][2], acc[nt][3]);
    }
}

// ----------------------------------------------------------------------------
// GEMM2: g_t16 = fp16(h @ [Wmu|Wlv])   [NN,64]x[64,64], tf32 mma (h in g_agg)
// ----------------------------------------------------------------------------
__global__ void k_gemm2(const float* __restrict__ Wmu, const float* __restrict__ Wlv) {
    __shared__ float sx[64][36];
    __shared__ float sw[64][36];   // [n][k]
    int tid = threadIdx.x;
    int warp = tid >> 5, lane = tid & 31;
    int g = lane >> 2, tg = lane & 3;
    long long bm0 = (long long)blockIdx.x * 64;

    float acc[8][4];
#pragma unroll
    for (int nt = 0; nt < 8; nt++)
#pragma unroll
        for (int q = 0; q < 4; q++) acc[nt][q] = 0.0f;

    for (int k0 = 0; k0 < HID_F; k0 += 32) {
        __syncthreads();
#pragma unroll
        for (int j = 0; j < 4; j++) {
            int idx = tid + j * 128;
            int r = idx >> 3, c4 = idx & 7;
            long long row = bm0 + r;
            float4 v = make_float4(0.f, 0.f, 0.f, 0.f);
            if (row < NN) v = *(const float4*)(g_agg + row * HID_F + k0 + c4 * 4);
            *(float4*)&sx[r][c4 * 4] = cvt4(v);
        }
#pragma unroll
        for (int j = 0; j < 4; j++) {
            int idx = tid + j * 128;
            int kr = idx >> 4, c4 = idx & 15;
            const float* Wsrc = (c4 < 8) ? Wmu : Wlv;
            int cc4 = (c4 < 8) ? c4 : (c4 - 8);
            float4 v = *(const float4*)(Wsrc + (long long)(k0 + kr) * 32 + cc4 * 4);
            float4 c = cvt4(v);
            sw[c4 * 4 + 0][kr] = c.x;
            sw[c4 * 4 + 1][kr] = c.y;
            sw[c4 * 4 + 2][kr] = c.z;
            sw[c4 * 4 + 3][kr] = c.w;
        }
        __syncthreads();
#pragma unroll
        for (int kk = 0; kk < 32; kk += 8) {
            unsigned a[4];
            a[0] = __float_as_uint(sx[warp * 16 + g][kk + tg]);
            a[1] = __float_as_uint(sx[warp * 16 + g + 8][kk + tg]);
            a[2] = __float_as_uint(sx[warp * 16 + g][kk + tg + 4]);
            a[3] = __float_as_uint(sx[warp * 16 + g + 8][kk + tg + 4]);
#pragma unroll
            for (int nt = 0; nt < 8; nt++) {
                unsigned b[2];
                b[0] = __float_as_uint(sw[nt * 8 + g][kk + tg]);
                b[1] = __float_as_uint(sw[nt * 8 + g][kk + tg + 4]);
                mma_tf32(acc[nt], a, b);
            }
        }
    }
    long long r0 = bm0 + warp * 16 + g;
#pragma unroll
    for (int nt = 0; nt < 8; nt++) {
        int c2 = nt * 4 + tg;
        if (r0 < NN)     g_t16[r0 * 32 + c2]       = __floats2half2_rn(acc[nt][0], acc[nt][1]);
        if (r0 + 8 < NN) g_t16[(r0 + 8) * 32 + c2] = __floats2half2_rn(acc[nt][2], acc[nt][3]);
    }
}

// ----------------------------------------------------------------------------
// CSR segment-sum aggregation: one warp per node; FOUR edge lanes per step
// (quad scheme). Each edge served by 8 lanes x 16 B (8 fp16 feats per lane).
// fp32 accumulation.
// ----------------------------------------------------------------------------
__device__ __forceinline__ void acc_row(float* acc, uint4 r, float nj) {
    half2* hp = (half2*)&r;
#pragma unroll
    for (int i = 0; i < 4; i++) {
        float2 f = __half22float2(hp[i]);
        acc[2 * i]     += f.x * nj;
        acc[2 * i + 1] += f.y * nj;
    }
}

__global__ void k_agg1(const float* __restrict__ b1) {
    int w = (blockIdx.x * blockDim.x + threadIdx.x) >> 5;
    int lane = threadIdx.x & 31;
    if (w >= NN) return;
    int q = lane >> 3, l8 = lane & 7;

    const uint4* t = (const uint4*)g_t16;   // 8 x uint4 per 128-B row
    float acc[8];
#pragma unroll
    for (int i = 0; i < 8; i++) acc[i] = 0.0f;
    if (q == 0) {
        float dv = g_dinv[w];
        acc_row(acc, t[(long long)w * 8 + l8], dv * dv);   // self-loop term
    }

    int beg = g_rowptr[w], end = g_rowptr[w + 1];
    for (int base = beg; base < end; base += 32) {
        int n = min(32, end - base);
        int2 e = make_int2(0, 0);
        if (lane < n) e = g_csr[base + lane];
        int steps = (n + 3) >> 2;
        for (int j = 0; j < steps; j++) {
            int idx = 4 * j + q;
            int   sj = __shfl_sync(0xffffffffu, e.x, idx);
            float nj = __int_as_float(__shfl_sync(0xffffffffu, e.y, idx));
            if (idx < n) acc_row(acc, t[(long long)sj * 8 + l8], nj);
        }
    }
#pragma unroll
    for (int i = 0; i < 8; i++) {
        acc[i] += __shfl_xor_sync(0xffffffffu, acc[i], 8);
        acc[i] += __shfl_xor_sync(0xffffffffu, acc[i], 16);
    }
    if (lane < 8) {    // q==0 lanes hold the sums for feats l8*8 .. l8*8+7
        float4 ba = ((const float4*)b1)[l8 * 2];
        float4 bb = ((const float4*)b1)[l8 * 2 + 1];
        float4 r0 = make_float4(fmaxf(acc[0] + ba.x, 0.f), fmaxf(acc[1] + ba.y, 0.f),
                                fmaxf(acc[2] + ba.z, 0.f), fmaxf(acc[3] + ba.w, 0.f));
        float4 r1 = make_float4(fmaxf(acc[4] + bb.x, 0.f), fmaxf(acc[5] + bb.y, 0.f),
                                fmaxf(acc[6] + bb.z, 0.f), fmaxf(acc[7] + bb.w, 0.f));
        ((float4*)g_agg)[(long long)w * 16 + l8 * 2]     = r0;
        ((float4*)g_agg)[(long long)w * 16 + l8 * 2 + 1] = r1;
    }
}

__global__ void k_agg2(const float* __restrict__ bmu, const float* __restrict__ blv,
                       float* __restrict__ out) {
    int w = (blockIdx.x * blockDim.x + threadIdx.x) >> 5;
    int lane = threadIdx.x & 31;
    if (w >= NN) return;
    int q = lane >> 3, l8 = lane & 7;

    const uint4* t = (const uint4*)g_t16;
    float acc[8];
#pragma unroll
    for (int i = 0; i < 8; i++) acc[i] = 0.0f;
    if (q == 0) {
        float dv = g_dinv[w];
        acc_row(acc, t[(long long)w * 8 + l8], dv * dv);
    }

    int beg = g_rowptr[w], end = g_rowptr[w + 1];
    for (int base = beg; base < end; base += 32) {
        int n = min(32, end - base);
        int2 e = make_int2(0, 0);
        if (lane < n) e = g_csr[base + lane];
        int steps = (n + 3) >> 2;
        for (int j = 0; j < steps; j++) {
            int idx = 4 * j + q;
            int   sj = __shfl_sync(0xffffffffu, e.x, idx);
            float nj = __int_as_float(__shfl_sync(0xffffffffu, e.y, idx));
            if (idx < n) acc_row(acc, t[(long long)sj * 8 + l8], nj);
        }
    }
#pragma unroll
    for (int i = 0; i < 8; i++) {
        acc[i] += __shfl_xor_sync(0xffffffffu, acc[i], 8);
        acc[i] += __shfl_xor_sync(0xffffffffu, acc[i], 16);
    }
    if (lane < 8) {    // feats l8*8..l8*8+7 : l8<4 -> mu cols, else logvar cols
        float4* o4 = (float4*)out;
        if (l8 < 4) {
            float4 ba = ((const float4*)bmu)[l8 * 2];
            float4 bb = ((const float4*)bmu)[l8 * 2 + 1];
            o4[(long long)w * 8 + l8 * 2]     = make_float4(acc[0] + ba.x, acc[1] + ba.y,
                                                            acc[2] + ba.z, acc[3] + ba.w);
            o4[(long long)w * 8 + l8 * 2 + 1] = make_float4(acc[4] + bb.x, acc[5] + bb.y,
                                                            acc[6] + bb.z, acc[7] + bb.w);
        } else {
            int l = l8 - 4;
            float4 ba = ((const float4*)blv)[l * 2];
            float4 bb = ((const float4*)blv)[l * 2 + 1];
            o4[(long long)NN * 8 + (long long)w * 8 + l * 2]     =
                make_float4(acc[0] + ba.x, acc[1] + ba.y, acc[2] + ba.z, acc[3] + ba.w);
            o4[(long long)NN * 8 + (long long)w * 8 + l * 2 + 1] =
                make_float4(acc[4] + bb.x, acc[5] + bb.y, acc[6] + bb.z, acc[7] + bb.w);
        }
    }
}

// ----------------------------------------------------------------------------
// Launch: CSR chain forked onto a side stream, overlapping GEMM1.
// ----------------------------------------------------------------------------
static cudaStream_t g_s2 = 0;
static cudaEvent_t  g_ev_fork = 0, g_ev_join = 0;

extern "C" void kernel_launch(void* const* d_in, const int* in_sizes, int n_in,
                              void* d_out, int out_size) {
    const float* x   = (const float*)d_in[0];
    const void*  ei  = d_in[1];
    const float* W1  = (const float*)d_in[2];
    const float* b1  = (const float*)d_in[3];
    const float* Wmu = (const float*)d_in[4];
    const float* bmu = (const float*)d_in[5];
    const float* Wlv = (const float*)d_in[6];
    const float* blv = (const float*)d_in[7];
    float* out = (float*)d_out;

    if (g_s2 == 0) {
        cudaStreamCreateWithFlags(&g_s2, cudaStreamNonBlocking);
        cudaEventCreateWithFlags(&g_ev_fork, cudaEventDisableTiming);
        cudaEventCreateWithFlags(&g_ev_join, cudaEventDisableTiming);
    }

    const int T = 256;
    const int gN = (NN + T - 1) / T;
    const int gE = (EE + T - 1) / T;
    const int gW = (NN * 32 + T - 1) / T;     // warp-per-node kernels
    const int gG = (NN + 63) / 64;            // tf32 GEMM blocks (BM=64)

    // Fork: CSR build chain on side stream
    cudaEventRecord(g_ev_fork, 0);
    cudaStreamWaitEvent(g_s2, g_ev_fork, 0);
    k_detect_zero<<<gN, T, 0, g_s2>>>(ei);
    k_hist<<<gE, T, 0, g_s2>>>(ei);
    k_scan1<<<SCAN_NB, SCAN_B, 0, g_s2>>>();
    k_scan3<<<SCAN_NB, SCAN_B, 0, g_s2>>>();
    k_scatter<<<gE, T, 0, g_s2>>>(ei);
    cudaEventRecord(g_ev_join, g_s2);

    // Main stream: GEMM1 overlaps the CSR chain
    k_gemm1<<<gG, 128>>>(x, W1);

    // Join: agg1 needs both GEMM1 output and CSR
    cudaStreamWaitEvent(0, g_ev_join, 0);
    k_agg1<<<gW, T>>>(b1);

    // Layer 2
    k_gemm2<<<gG, 128>>>(Wmu, Wlv);
    k_agg2<<<gW, T>>>(bmu, blv, out);
}